// round 1
// baseline (speedup 1.0000x reference)
#include <cuda_runtime.h>
#include <math.h>

// ---------------- problem constants ----------------
#define Bc   32
#define Hc   56
#define Wc   56
#define Cc   192
#define WSc  7
#define SSc  3
#define NHc  6
#define Nc   49          // WS*WS
#define HDc  32          // C/NH
#define HIDc 768         // 4*C
#define NWIN 64          // (H/WS)*(W/WS)
#define Mrows (Bc * Hc * Wc)   // 100352
#define SCALEc 0.17677669529663687f  // 32^-0.5
#define EPSc 1e-5f

// ---------------- scratch (device globals, no allocs) ----------------
__device__ float g_xw  [(size_t)Mrows * Cc];    // LN1 + shifted window layout
__device__ float g_qkv [(size_t)Mrows * 3 * Cc];
__device__ float g_attn[(size_t)Mrows * Cc];    // attention output (window layout)
__device__ float g_h   [(size_t)Mrows * Cc];    // shortcut + proj (token layout)
__device__ float g_ln2 [(size_t)Mrows * Cc];
__device__ float g_fc1 [(size_t)Mrows * HIDc];

// Map a window-layout row r (0..Mrows-1) to (batch b, token index within batch).
// Window layout row r: window b_ = r/49, in-window n = r%49.
// Shifted coords hs=wr*7+n/7, ws=wc*7+n%7 ; original/final token = ((hs+3)%56, (ws+3)%56).
__device__ __forceinline__ int win_to_token(int r, int& b) {
    int b_ = r / Nc;
    int n  = r - b_ * Nc;
    b = b_ >> 6;                  // /64 windows per image
    int wi = b_ & 63;
    int wr = wi >> 3, wc = wi & 7;
    int hs = wr * WSc + n / WSc;
    int ws = wc * WSc + n % WSc;
    int ho = hs + SSc; if (ho >= Hc) ho -= Hc;
    int wo = ws + SSc; if (wo >= Wc) wo -= Wc;
    return ho * Wc + wo;
}

// ---------------- LayerNorm kernels (warp per row, C=192 = 6*32) ----------------
__global__ void __launch_bounds__(256) ln1_kernel(const float* __restrict__ x,
                                                  const float* __restrict__ g,
                                                  const float* __restrict__ bta,
                                                  float* __restrict__ out) {
    int warp = (blockIdx.x * blockDim.x + threadIdx.x) >> 5;
    int lane = threadIdx.x & 31;
    if (warp >= Mrows) return;
    int b; int tok = win_to_token(warp, b);
    const float* src = x + ((size_t)b * (Hc * Wc) + tok) * Cc;
    float e[6]; float s = 0.f, ss = 0.f;
#pragma unroll
    for (int k = 0; k < 6; k++) { e[k] = src[lane + 32 * k]; s += e[k]; ss += e[k] * e[k]; }
#pragma unroll
    for (int o = 16; o > 0; o >>= 1) {
        s  += __shfl_xor_sync(0xffffffffu, s,  o);
        ss += __shfl_xor_sync(0xffffffffu, ss, o);
    }
    float mu = s * (1.f / Cc);
    float var = ss * (1.f / Cc) - mu * mu;
    float rs = rsqrtf(var + EPSc);
    float* dst = out + (size_t)warp * Cc;
#pragma unroll
    for (int k = 0; k < 6; k++) {
        int c = lane + 32 * k;
        dst[c] = (e[k] - mu) * rs * g[c] + bta[c];
    }
}

__global__ void __launch_bounds__(256) ln2_kernel(const float* __restrict__ x,
                                                  const float* __restrict__ g,
                                                  const float* __restrict__ bta,
                                                  float* __restrict__ out) {
    int warp = (blockIdx.x * blockDim.x + threadIdx.x) >> 5;
    int lane = threadIdx.x & 31;
    if (warp >= Mrows) return;
    const float* src = x + (size_t)warp * Cc;
    float e[6]; float s = 0.f, ss = 0.f;
#pragma unroll
    for (int k = 0; k < 6; k++) { e[k] = src[lane + 32 * k]; s += e[k]; ss += e[k] * e[k]; }
#pragma unroll
    for (int o = 16; o > 0; o >>= 1) {
        s  += __shfl_xor_sync(0xffffffffu, s,  o);
        ss += __shfl_xor_sync(0xffffffffu, ss, o);
    }
    float mu = s * (1.f / Cc);
    float var = ss * (1.f / Cc) - mu * mu;
    float rs = rsqrtf(var + EPSc);
    float* dst = out + (size_t)warp * Cc;
#pragma unroll
    for (int k = 0; k < 6; k++) {
        int c = lane + 32 * k;
        dst[c] = (e[k] - mu) * rs * g[c] + bta[c];
    }
}

// ---------------- tiled SGEMM: C[M,N] = A[M,K] @ W[N,K]^T + bias, fused epilogues ----
// EPI 0: plain (qkv)
// EPI 1: scatter to token layout + shortcut add (proj):   C[b,tok,c] = add[b,tok,c] + v
// EPI 2: exact GELU (fc1)
// EPI 3: residual add, same layout (fc2 -> d_out)
#define BMg 64
#define BNg 64
#define BKg 16
#define PADg 4

template<int EPI>
__global__ void __launch_bounds__(256) gemm_kernel(const float* __restrict__ A,
                                                   const float* __restrict__ Bw,
                                                   const float* __restrict__ bias,
                                                   const float* __restrict__ add,
                                                   float* __restrict__ C,
                                                   int M, int N, int K) {
    __shared__ float As[BKg][BMg + PADg];
    __shared__ float Bs[BKg][BNg + PADg];
    int bm = blockIdx.y, bn = blockIdx.x;
    int tid = threadIdx.x;
    int tx = tid & 15;      // 16 column groups
    int ty = tid >> 4;      // 16 row groups
    const float* Ab = A  + (size_t)bm * BMg * K;
    const float* Bb = Bw + (size_t)bn * BNg * K;

    float acc[4][4] = {};
    int lk = tid & 15;      // k slot in tile
    int lm = tid >> 4;      // row, strided by 16

    for (int k0 = 0; k0 < K; k0 += BKg) {
#pragma unroll
        for (int i = 0; i < 4; i++) {
            As[lk][lm + 16 * i] = Ab[(size_t)(lm + 16 * i) * K + k0 + lk];
            Bs[lk][lm + 16 * i] = Bb[(size_t)(lm + 16 * i) * K + k0 + lk];
        }
        __syncthreads();
#pragma unroll
        for (int kk = 0; kk < BKg; kk++) {
            float4 a4 = *(const float4*)&As[kk][ty * 4];
            float4 b4 = *(const float4*)&Bs[kk][tx * 4];
            float a[4] = {a4.x, a4.y, a4.z, a4.w};
            float b[4] = {b4.x, b4.y, b4.z, b4.w};
#pragma unroll
            for (int i = 0; i < 4; i++)
#pragma unroll
                for (int j = 0; j < 4; j++)
                    acc[i][j] += a[i] * b[j];
        }
        __syncthreads();
    }

    int row0 = bm * BMg + ty * 4;
    int col0 = bn * BNg + tx * 4;
#pragma unroll
    for (int i = 0; i < 4; i++) {
        int r = row0 + i;
        if (EPI == 1) {
            int b; int tok = win_to_token(r, b);
            size_t base = ((size_t)b * (Hc * Wc) + tok) * Cc;
#pragma unroll
            for (int j = 0; j < 4; j++) {
                int c = col0 + j;
                C[base + c] = add[base + c] + acc[i][j] + bias[c];
            }
        } else {
            size_t base = (size_t)r * N;
#pragma unroll
            for (int j = 0; j < 4; j++) {
                int c = col0 + j;
                float v = acc[i][j] + bias[c];
                if (EPI == 2) v = 0.5f * v * (1.0f + erff(v * 0.70710678118654752f));
                if (EPI == 3) v += add[base + c];
                C[base + c] = v;
            }
        }
    }
}

// ---------------- attention: one block per (window, head) ----------------
__device__ __forceinline__ int regionOf(int p) {
    return (p < Hc - WSc) ? 0 : ((p < Hc - SSc) ? 1 : 2);
}

__global__ void __launch_bounds__(256) attn_kernel(const float* __restrict__ qkv,
                                                   const float* __restrict__ rpb,
                                                   float* __restrict__ out) {
    int bh = blockIdx.x;
    int b_ = bh / NHc;
    int h  = bh - b_ * NHc;
    int tid = threadIdx.x;

    __shared__ float qs[Nc * HDc];
    __shared__ float ks[Nc * HDc];
    __shared__ float vs[Nc * HDc];
    __shared__ float S[Nc * 50];          // padded row stride

    // load q (pre-scaled), k, v
    for (int idx = tid; idx < Nc * HDc; idx += 256) {
        int n = idx >> 5, d = idx & 31;
        size_t rb = ((size_t)b_ * Nc + n) * (3 * Cc) + h * HDc + d;
        qs[idx] = qkv[rb] * SCALEc;
        ks[idx] = qkv[rb + Cc];
        vs[idx] = qkv[rb + 2 * Cc];
    }
    __syncthreads();

    // scores + bias + mask
    int wi = b_ & 63;
    int wr = wi >> 3, wc = wi & 7;
    for (int idx = tid; idx < Nc * Nc; idx += 256) {
        int i = idx / Nc, j = idx - i * Nc;
        float s = 0.f;
        const float* qi = qs + i * HDc;
        const float* kj = ks + j * HDc;
#pragma unroll
        for (int d = 0; d < HDc; d++) s += qi[d] * kj[d];
        int ri = i / WSc, ci = i % WSc;
        int rj = j / WSc, cj = j % WSc;
        int rel = (ri - rj + WSc - 1) * (2 * WSc - 1) + (ci - cj + WSc - 1);
        s += rpb[rel * NHc + h];
        // shift mask
        int cnti = regionOf(wr * WSc + ri) * 3 + regionOf(wc * WSc + ci);
        int cntj = regionOf(wr * WSc + rj) * 3 + regionOf(wc * WSc + cj);
        if (cnti != cntj) s -= 100.0f;
        S[i * 50 + j] = s;
    }
    __syncthreads();

    // softmax: warp per row
    int w = tid >> 5, lane = tid & 31;
    for (int i = w; i < Nc; i += 8) {
        float* row = S + i * 50;
        float mx = -1e30f;
        for (int j = lane; j < Nc; j += 32) mx = fmaxf(mx, row[j]);
#pragma unroll
        for (int o = 16; o > 0; o >>= 1) mx = fmaxf(mx, __shfl_xor_sync(0xffffffffu, mx, o));
        float sum = 0.f;
        for (int j = lane; j < Nc; j += 32) {
            float e = __expf(row[j] - mx);
            row[j] = e;
            sum += e;
        }
#pragma unroll
        for (int o = 16; o > 0; o >>= 1) sum += __shfl_xor_sync(0xffffffffu, sum, o);
        float inv = 1.0f / sum;
        for (int j = lane; j < Nc; j += 32) row[j] *= inv;
    }
    __syncthreads();

    // P @ V
    for (int idx = tid; idx < Nc * HDc; idx += 256) {
        int i = idx >> 5, d = idx & 31;
        const float* row = S + i * 50;
        float s = 0.f;
#pragma unroll
        for (int j = 0; j < Nc; j++) s += row[j] * vs[j * HDc + d];
        out[((size_t)b_ * Nc + i) * Cc + h * HDc + d] = s;
    }
}

// ---------------- launch ----------------
extern "C" void kernel_launch(void* const* d_in, const int* in_sizes, int n_in,
                              void* d_out, int out_size) {
    const float* x       = (const float*)d_in[0];
    const float* norm1_g = (const float*)d_in[1];
    const float* norm1_b = (const float*)d_in[2];
    const float* qkv_w   = (const float*)d_in[3];
    const float* qkv_b   = (const float*)d_in[4];
    const float* proj_w  = (const float*)d_in[5];
    const float* proj_b  = (const float*)d_in[6];
    const float* rpb     = (const float*)d_in[7];
    const float* norm2_g = (const float*)d_in[8];
    const float* norm2_b = (const float*)d_in[9];
    const float* fc1_w   = (const float*)d_in[10];
    const float* fc1_b   = (const float*)d_in[11];
    const float* fc2_w   = (const float*)d_in[12];
    const float* fc2_b   = (const float*)d_in[13];
    float* outp = (float*)d_out;

    float *p_xw, *p_qkv, *p_attn, *p_h, *p_ln2, *p_fc1;
    cudaGetSymbolAddress((void**)&p_xw,  g_xw);
    cudaGetSymbolAddress((void**)&p_qkv, g_qkv);
    cudaGetSymbolAddress((void**)&p_attn,g_attn);
    cudaGetSymbolAddress((void**)&p_h,   g_h);
    cudaGetSymbolAddress((void**)&p_ln2, g_ln2);
    cudaGetSymbolAddress((void**)&p_fc1, g_fc1);

    const int lnBlocks = (Mrows * 32 + 255) / 256;   // warp per row

    // 1) LN1 + shift + window partition
    ln1_kernel<<<lnBlocks, 256>>>(x, norm1_g, norm1_b, p_xw);

    // 2) QKV GEMM: (100352,192) @ (576,192)^T
    gemm_kernel<0><<<dim3(3 * Cc / BNg, Mrows / BMg), 256>>>(p_xw, qkv_w, qkv_b, nullptr,
                                                             p_qkv, Mrows, 3 * Cc, Cc);

    // 3) windowed attention
    attn_kernel<<<Bc * NWIN * NHc, 256>>>(p_qkv, rpb, p_attn);

    // 4) proj GEMM + window reverse + roll back + shortcut
    gemm_kernel<1><<<dim3(Cc / BNg, Mrows / BMg), 256>>>(p_attn, proj_w, proj_b, x,
                                                         p_h, Mrows, Cc, Cc);

    // 5) LN2
    ln2_kernel<<<lnBlocks, 256>>>(p_h, norm2_g, norm2_b, p_ln2);

    // 6) FC1 + GELU
    gemm_kernel<2><<<dim3(HIDc / BNg, Mrows / BMg), 256>>>(p_ln2, fc1_w, fc1_b, nullptr,
                                                           p_fc1, Mrows, HIDc, Cc);

    // 7) FC2 + residual -> out
    gemm_kernel<3><<<dim3(Cc / BNg, Mrows / BMg), 256>>>(p_fc1, fc2_w, fc2_b, p_h,
                                                         outp, Mrows, Cc, HIDc);
}

// round 7
// speedup vs baseline: 2.1562x; 2.1562x over previous
#include <cuda_runtime.h>
#include <cuda_fp16.h>
#include <mma.h>
#include <math.h>
#include <stdint.h>

using namespace nvcuda;

// ---------------- problem constants ----------------
#define Bc   32
#define Hc   56
#define Wc   56
#define Cc   192
#define WSc  7
#define SSc  3
#define NHc  6
#define Nc   49
#define HDc  32
#define HIDc 768
#define NWIN 64
#define Mrows (Bc * Hc * Wc)   // 100352
#define SCALEc 0.17677669529663687f
#define EPSc 1e-5f

// ---------------- scratch (device globals, no allocs) ----------------
__device__ __half g_xw_h  [(size_t)Mrows * Cc];
__device__ float  g_qkv   [(size_t)Mrows * 3 * Cc];
__device__ __half g_attn_h[(size_t)Mrows * Cc];
__device__ float  g_h     [(size_t)Mrows * Cc];
__device__ __half g_ln2_h [(size_t)Mrows * Cc];
__device__ __half g_fc1_h [(size_t)Mrows * HIDc];
__device__ __half g_wqkv_h[3 * Cc * Cc];
__device__ __half g_wproj_h[Cc * Cc];
__device__ __half g_wfc1_h[HIDc * Cc];
__device__ __half g_wfc2_h[Cc * HIDc];

// ---------------- index helpers ----------------
__device__ __forceinline__ int win_to_token(int r, int& b) {
    int b_ = r / Nc;
    int n  = r - b_ * Nc;
    b = b_ >> 6;
    int wi = b_ & 63;
    int wr = wi >> 3, wc = wi & 7;
    int hs = wr * WSc + n / WSc;
    int ws = wc * WSc + n % WSc;
    int ho = hs + SSc; if (ho >= Hc) ho -= Hc;
    int wo = ws + SSc; if (wo >= Wc) wo -= Wc;
    return ho * Wc + wo;
}
__device__ __forceinline__ int regionOf(int p) {
    return (p < Hc - WSc) ? 0 : ((p < Hc - SSc) ? 1 : 2);
}

// ---------------- conversion: fp32 -> fp16 ----------------
__global__ void __launch_bounds__(256) f2h_kernel(const float* __restrict__ in,
                                                  __half* __restrict__ out, int n) {
    int i = blockIdx.x * blockDim.x + threadIdx.x;
    if (i < n) out[i] = __float2half(in[i]);
}

// ---------------- LayerNorm kernels (warp per row), output fp16 ----------------
// MODE 0: gather via win_to_token (LN1 + shift + window partition). MODE 1: plain (LN2).
template<int MODE>
__global__ void __launch_bounds__(256) ln_kernel(const float* __restrict__ x,
                                                 const float* __restrict__ g,
                                                 const float* __restrict__ bta,
                                                 __half* __restrict__ out) {
    int warp = (blockIdx.x * blockDim.x + threadIdx.x) >> 5;
    int lane = threadIdx.x & 31;
    if (warp >= Mrows) return;
    const float* src;
    if (MODE == 0) {
        int b; int tok = win_to_token(warp, b);
        src = x + ((size_t)b * (Hc * Wc) + tok) * Cc;
    } else {
        src = x + (size_t)warp * Cc;
    }
    float e[6]; float s = 0.f, ss = 0.f;
#pragma unroll
    for (int k = 0; k < 6; k++) { e[k] = src[lane + 32 * k]; s += e[k]; ss += e[k] * e[k]; }
#pragma unroll
    for (int o = 16; o > 0; o >>= 1) {
        s  += __shfl_xor_sync(0xffffffffu, s,  o);
        ss += __shfl_xor_sync(0xffffffffu, ss, o);
    }
    float mu = s * (1.f / Cc);
    float var = ss * (1.f / Cc) - mu * mu;
    float rs = rsqrtf(var + EPSc);
    __half* dst = out + (size_t)warp * Cc;
#pragma unroll
    for (int k = 0; k < 6; k++) {
        int c = lane + 32 * k;
        dst[c] = __float2half((e[k] - mu) * rs * g[c] + bta[c]);
    }
}

// ---------------- wmma HMMA GEMM: C[M,N] = A[M,K] @ W[N,K]^T + bias ----------------
// Block: 256 threads = 8 warps. Tile 128x64. Warp tile 32x32 (2x2 wmma 16x16x16).
// BK = 32. fp16 operands, fp32 accumulate.
// EPI 0: fp32 out (qkv). EPI 1: scatter + shortcut (proj -> h). EPI 2: GELU -> half (fc1).
// EPI 3: residual add -> fp32 out (fc2 -> d_out).
#define BKw 32
#define ASTR 40            // halves: 32 + 8 pad (80B rows, 16B aligned)
#define BSTR 40
#define STG  72            // floats: 64 + 8 pad (288B rows, 16B aligned)
#define SM_A_OFF 0
#define SM_B_OFF (128 * ASTR * 2)                 // 10240
#define SMEM_AB  (SM_B_OFF + 64 * BSTR * 2)       // 15360
#define SMEM_STG (128 * STG * 4)                  // 36864
#define SMEM_TOT (SMEM_STG > SMEM_AB ? SMEM_STG : SMEM_AB)

template<int EPI>
__global__ void __launch_bounds__(256) hgemm_kernel(const __half* __restrict__ A,
                                                    const __half* __restrict__ Bw,
                                                    const float* __restrict__ bias,
                                                    const float* __restrict__ add,
                                                    float* __restrict__ outF,
                                                    __half* __restrict__ outH,
                                                    int N, int K) {
    extern __shared__ char smem[];
    __half* As = (__half*)(smem + SM_A_OFF);
    __half* Bs = (__half*)(smem + SM_B_OFF);
    float*  stage = (float*)smem;

    int tid = threadIdx.x;
    int wid = tid >> 5;
    int wr = wid & 3;          // warp row: 4 x 32 = 128
    int wc = wid >> 2;         // warp col: 2 x 32 = 64
    int row0 = blockIdx.y * 128;
    int col0 = blockIdx.x * 64;

    wmma::fragment<wmma::accumulator, 16, 16, 16, float> cf[2][2];
#pragma unroll
    for (int i = 0; i < 2; i++)
#pragma unroll
        for (int j = 0; j < 2; j++)
            wmma::fill_fragment(cf[i][j], 0.0f);

    const __half* Ab = A  + (size_t)row0 * K;
    const __half* Bb = Bw + (size_t)col0 * K;

    for (int k0 = 0; k0 < K; k0 += BKw) {
        // load A tile: 128 x 32 halves = 512 uint4
        for (int idx = tid; idx < 512; idx += 256) {
            int r = idx >> 2, seg = idx & 3;
            *(uint4*)(As + r * ASTR + seg * 8) =
                *(const uint4*)(Ab + (size_t)r * K + k0 + seg * 8);
        }
        // load B tile: 64 x 32 halves = 256 uint4
        {
            int r = tid >> 2, seg = tid & 3;
            *(uint4*)(Bs + r * BSTR + seg * 8) =
                *(const uint4*)(Bb + (size_t)r * K + k0 + seg * 8);
        }
        __syncthreads();

#pragma unroll
        for (int ks = 0; ks < 2; ks++) {
            wmma::fragment<wmma::matrix_a, 16, 16, 16, __half, wmma::row_major> af[2];
            wmma::fragment<wmma::matrix_b, 16, 16, 16, __half, wmma::col_major> bf[2];
#pragma unroll
            for (int i = 0; i < 2; i++)
                wmma::load_matrix_sync(af[i], As + (wr * 32 + i * 16) * ASTR + ks * 16, ASTR);
#pragma unroll
            for (int j = 0; j < 2; j++)
                wmma::load_matrix_sync(bf[j], Bs + (wc * 32 + j * 16) * BSTR + ks * 16, BSTR);
#pragma unroll
            for (int i = 0; i < 2; i++)
#pragma unroll
                for (int j = 0; j < 2; j++)
                    wmma::mma_sync(cf[i][j], af[i], bf[j], cf[i][j]);
        }
        __syncthreads();
    }

    // stage accumulators to smem (fp32), then fused coalesced epilogue
#pragma unroll
    for (int i = 0; i < 2; i++)
#pragma unroll
        for (int j = 0; j < 2; j++)
            wmma::store_matrix_sync(stage + (wr * 32 + i * 16) * STG + wc * 32 + j * 16,
                                    cf[i][j], STG, wmma::mem_row_major);
    __syncthreads();

    for (int idx = tid; idx < 128 * 16; idx += 256) {
        int rr = idx >> 4, v = idx & 15;
        float4 val = *(float4*)&stage[rr * STG + 4 * v];
        int m  = row0 + rr;
        int c0 = col0 + 4 * v;
        float4 b4 = *(const float4*)&bias[c0];
        val.x += b4.x; val.y += b4.y; val.z += b4.z; val.w += b4.w;
        if (EPI == 0) {
            *(float4*)&outF[(size_t)m * N + c0] = val;
        } else if (EPI == 1) {
            int b; int tok = win_to_token(m, b);
            size_t base = ((size_t)b * (Hc * Wc) + tok) * Cc + c0;
            float4 a4 = *(const float4*)&add[base];
            val.x += a4.x; val.y += a4.y; val.z += a4.z; val.w += a4.w;
            *(float4*)&outF[base] = val;
        } else if (EPI == 2) {
            const float inv_s2 = 0.70710678118654752f;
            val.x = 0.5f * val.x * (1.0f + erff(val.x * inv_s2));
            val.y = 0.5f * val.y * (1.0f + erff(val.y * inv_s2));
            val.z = 0.5f * val.z * (1.0f + erff(val.z * inv_s2));
            val.w = 0.5f * val.w * (1.0f + erff(val.w * inv_s2));
            __half2 h0 = __floats2half2_rn(val.x, val.y);
            __half2 h1 = __floats2half2_rn(val.z, val.w);
            uint2 pk; pk.x = *(uint32_t*)&h0; pk.y = *(uint32_t*)&h1;
            *(uint2*)&outH[(size_t)m * HIDc + c0] = pk;
        } else {  // EPI 3
            size_t base = (size_t)m * Cc + c0;
            float4 a4 = *(const float4*)&add[base];
            val.x += a4.x; val.y += a4.y; val.z += a4.z; val.w += a4.w;
            *(float4*)&outF[base] = val;
        }
    }
}

// ---------------- attention: one block per (window, head) ----------------
__global__ void __launch_bounds__(256) attn_kernel(const float* __restrict__ qkv,
                                                   const float* __restrict__ rpb,
                                                   __half* __restrict__ out) {
    int bh = blockIdx.x;
    int b_ = bh / NHc;
    int h  = bh - b_ * NHc;
    int tid = threadIdx.x;

    __shared__ float qs[Nc * HDc];
    __shared__ float ks[Nc * HDc];
    __shared__ float vs[Nc * HDc];
    __shared__ float S[Nc * 50];

    for (int idx = tid; idx < Nc * HDc; idx += 256) {
        int n = idx >> 5, d = idx & 31;
        size_t rb = ((size_t)b_ * Nc + n) * (3 * Cc) + h * HDc + d;
        qs[idx] = qkv[rb] * SCALEc;
        ks[idx] = qkv[rb + Cc];
        vs[idx] = qkv[rb + 2 * Cc];
    }
    __syncthreads();

    int wi = b_ & 63;
    int wr = wi >> 3, wc = wi & 7;
    for (int idx = tid; idx < Nc * Nc; idx += 256) {
        int i = idx / Nc, j = idx - i * Nc;
        float s = 0.f;
        const float* qi = qs + i * HDc;
        const float* kj = ks + j * HDc;
#pragma unroll
        for (int d = 0; d < HDc; d++) s += qi[d] * kj[d];
        int ri = i / WSc, ci = i % WSc;
        int rj = j / WSc, cj = j % WSc;
        int rel = (ri - rj + WSc - 1) * (2 * WSc - 1) + (ci - cj + WSc - 1);
        s += rpb[rel * NHc + h];
        int cnti = regionOf(wr * WSc + ri) * 3 + regionOf(wc * WSc + ci);
        int cntj = regionOf(wr * WSc + rj) * 3 + regionOf(wc * WSc + cj);
        if (cnti != cntj) s -= 100.0f;
        S[i * 50 + j] = s;
    }
    __syncthreads();

    int w = tid >> 5, lane = tid & 31;
    for (int i = w; i < Nc; i += 8) {
        float* row = S + i * 50;
        float mx = -1e30f;
        for (int j = lane; j < Nc; j += 32) mx = fmaxf(mx, row[j]);
#pragma unroll
        for (int o = 16; o > 0; o >>= 1) mx = fmaxf(mx, __shfl_xor_sync(0xffffffffu, mx, o));
        float sum = 0.f;
        for (int j = lane; j < Nc; j += 32) {
            float e = __expf(row[j] - mx);
            row[j] = e;
            sum += e;
        }
#pragma unroll
        for (int o = 16; o > 0; o >>= 1) sum += __shfl_xor_sync(0xffffffffu, sum, o);
        float inv = 1.0f / sum;
        for (int j = lane; j < Nc; j += 32) row[j] *= inv;
    }
    __syncthreads();

    for (int idx = tid; idx < Nc * HDc; idx += 256) {
        int i = idx >> 5, d = idx & 31;
        const float* row = S + i * 50;
        float s = 0.f;
#pragma unroll
        for (int j = 0; j < Nc; j++) s += row[j] * vs[j * HDc + d];
        out[((size_t)b_ * Nc + i) * Cc + h * HDc + d] = __float2half(s);
    }
}

// ---------------- launch ----------------
extern "C" void kernel_launch(void* const* d_in, const int* in_sizes, int n_in,
                              void* d_out, int out_size) {
    const float* x       = (const float*)d_in[0];
    const float* norm1_g = (const float*)d_in[1];
    const float* norm1_b = (const float*)d_in[2];
    const float* qkv_w   = (const float*)d_in[3];
    const float* qkv_b   = (const float*)d_in[4];
    const float* proj_w  = (const float*)d_in[5];
    const float* proj_b  = (const float*)d_in[6];
    const float* rpb     = (const float*)d_in[7];
    const float* norm2_g = (const float*)d_in[8];
    const float* norm2_b = (const float*)d_in[9];
    const float* fc1_w   = (const float*)d_in[10];
    const float* fc1_b   = (const float*)d_in[11];
    const float* fc2_w   = (const float*)d_in[12];
    const float* fc2_b   = (const float*)d_in[13];
    float* outp = (float*)d_out;

    __half *p_xw, *p_attn, *p_ln2, *p_fc1, *p_wqkv, *p_wproj, *p_wfc1, *p_wfc2;
    float *p_qkv, *p_h;
    cudaGetSymbolAddress((void**)&p_xw,   g_xw_h);
    cudaGetSymbolAddress((void**)&p_qkv,  g_qkv);
    cudaGetSymbolAddress((void**)&p_attn, g_attn_h);
    cudaGetSymbolAddress((void**)&p_h,    g_h);
    cudaGetSymbolAddress((void**)&p_ln2,  g_ln2_h);
    cudaGetSymbolAddress((void**)&p_fc1,  g_fc1_h);
    cudaGetSymbolAddress((void**)&p_wqkv, g_wqkv_h);
    cudaGetSymbolAddress((void**)&p_wproj,g_wproj_h);
    cudaGetSymbolAddress((void**)&p_wfc1, g_wfc1_h);
    cudaGetSymbolAddress((void**)&p_wfc2, g_wfc2_h);

    // weight conversions (tiny)
    f2h_kernel<<<(3*Cc*Cc + 255)/256, 256>>>(qkv_w,  p_wqkv,  3*Cc*Cc);
    f2h_kernel<<<(Cc*Cc   + 255)/256, 256>>>(proj_w, p_wproj, Cc*Cc);
    f2h_kernel<<<(HIDc*Cc + 255)/256, 256>>>(fc1_w,  p_wfc1,  HIDc*Cc);
    f2h_kernel<<<(Cc*HIDc + 255)/256, 256>>>(fc2_w,  p_wfc2,  Cc*HIDc);

    const int lnBlocks = (Mrows * 32 + 255) / 256;
    const int smemB = SMEM_TOT;

    // 1) LN1 + shift + window partition (-> fp16)
    ln_kernel<0><<<lnBlocks, 256>>>(x, norm1_g, norm1_b, p_xw);

    // 2) QKV GEMM (HMMA): (100352,192) x (576,192)^T -> fp32
    hgemm_kernel<0><<<dim3(9, 784), 256, smemB>>>(p_xw, p_wqkv, qkv_b, nullptr,
                                                  p_qkv, nullptr, 3*Cc, Cc);

    // 3) windowed attention (fp32 in, fp16 out)
    attn_kernel<<<Bc * NWIN * NHc, 256>>>(p_qkv, rpb, p_attn);

    // 4) proj GEMM + window reverse + roll + shortcut -> fp32 h
    hgemm_kernel<1><<<dim3(3, 784), 256, smemB>>>(p_attn, p_wproj, proj_b, x,
                                                  p_h, nullptr, Cc, Cc);

    // 5) LN2 (-> fp16)
    ln_kernel<1><<<lnBlocks, 256>>>(p_h, norm2_g, norm2_b, p_ln2);

    // 6) FC1 + GELU (-> fp16)
    hgemm_kernel<2><<<dim3(12, 784), 256, smemB>>>(p_ln2, p_wfc1, fc1_b, nullptr,
                                                   nullptr, p_fc1, HIDc, Cc);

    // 7) FC2 + residual -> fp32 out
    hgemm_kernel<3><<<dim3(3, 784), 256, smemB>>>(p_fc1, p_wfc2, fc2_b, p_h,
                                                  outp, nullptr, Cc, HIDc);
}

// round 8
// speedup vs baseline: 2.2752x; 1.0552x over previous
#include <cuda_runtime.h>
#include <cuda_fp16.h>
#include <mma.h>
#include <math.h>
#include <stdint.h>

using namespace nvcuda;

// ---------------- problem constants ----------------
#define Bc   32
#define Hc   56
#define Wc   56
#define Cc   192
#define WSc  7
#define SSc  3
#define NHc  6
#define Nc   49
#define HDc  32
#define HIDc 768
#define NWIN 64
#define Mrows (Bc * Hc * Wc)   // 100352
#define SCALEc 0.17677669529663687f
#define EPSc 1e-5f

// ---------------- scratch (device globals, no allocs) ----------------
__device__ __half g_xw_h  [(size_t)Mrows * Cc];
__device__ __half g_qkv_h [(size_t)Mrows * 3 * Cc];
__device__ __half g_attn_h[(size_t)Mrows * Cc];
__device__ float  g_h     [(size_t)Mrows * Cc];
__device__ __half g_ln2_h [(size_t)Mrows * Cc];
__device__ __half g_fc1_h [(size_t)Mrows * HIDc];
__device__ __half g_wqkv_h[3 * Cc * Cc];
__device__ __half g_wproj_h[Cc * Cc];
__device__ __half g_wfc1_h[HIDc * Cc];
__device__ __half g_wfc2_h[Cc * HIDc];

// ---------------- index helpers ----------------
__device__ __forceinline__ int win_to_token(int r, int& b) {
    int b_ = r / Nc;
    int n  = r - b_ * Nc;
    b = b_ >> 6;
    int wi = b_ & 63;
    int wr = wi >> 3, wc = wi & 7;
    int hs = wr * WSc + n / WSc;
    int ws = wc * WSc + n % WSc;
    int ho = hs + SSc; if (ho >= Hc) ho -= Hc;
    int wo = ws + SSc; if (wo >= Wc) wo -= Wc;
    return ho * Wc + wo;
}
__device__ __forceinline__ int regionOf(int p) {
    return (p < Hc - WSc) ? 0 : ((p < Hc - SSc) ? 1 : 2);
}

__device__ __forceinline__ uint32_t smem_u32(const void* p) {
    uint32_t a;
    asm("{ .reg .u64 t; cvta.to.shared.u64 t, %1; cvt.u32.u64 %0, t; }" : "=r"(a) : "l"(p));
    return a;
}
__device__ __forceinline__ void cp_async16(uint32_t saddr, const void* g) {
    asm volatile("cp.async.cg.shared.global [%0], [%1], 16;" :: "r"(saddr), "l"(g));
}
#define CP_COMMIT() asm volatile("cp.async.commit_group;" ::: "memory")
#define CP_WAIT1()  asm volatile("cp.async.wait_group 1;" ::: "memory")
#define CP_WAIT0()  asm volatile("cp.async.wait_group 0;" ::: "memory")

// ---------------- fused weight conversion: fp32 -> fp16, all 4 weights ----------------
#define NQKV (3 * Cc * Cc)
#define NPRJ (Cc * Cc)
#define NFC1 (HIDc * Cc)
#define NFC2 (Cc * HIDc)
__global__ void __launch_bounds__(256) f2h4_kernel(const float* __restrict__ w0,
                                                   const float* __restrict__ w1,
                                                   const float* __restrict__ w2,
                                                   const float* __restrict__ w3,
                                                   __half* __restrict__ o0,
                                                   __half* __restrict__ o1,
                                                   __half* __restrict__ o2,
                                                   __half* __restrict__ o3) {
    int i = blockIdx.x * blockDim.x + threadIdx.x;
    if (i < NQKV) o0[i] = __float2half(w0[i]);
    int j = i - NQKV;
    if (j >= 0 && j < NPRJ) o1[j] = __float2half(w1[j]);
    int k = j - NPRJ;
    if (k >= 0 && k < NFC1) o2[k] = __float2half(w2[k]);
    int l = k - NFC1;
    if (l >= 0 && l < NFC2) o3[l] = __float2half(w3[l]);
}

// ---------------- LayerNorm kernels (warp per row), output fp16 ----------------
template<int MODE>
__global__ void __launch_bounds__(256) ln_kernel(const float* __restrict__ x,
                                                 const float* __restrict__ g,
                                                 const float* __restrict__ bta,
                                                 __half* __restrict__ out) {
    int warp = (blockIdx.x * blockDim.x + threadIdx.x) >> 5;
    int lane = threadIdx.x & 31;
    if (warp >= Mrows) return;
    const float* src;
    if (MODE == 0) {
        int b; int tok = win_to_token(warp, b);
        src = x + ((size_t)b * (Hc * Wc) + tok) * Cc;
    } else {
        src = x + (size_t)warp * Cc;
    }
    float e[6]; float s = 0.f, ss = 0.f;
#pragma unroll
    for (int k = 0; k < 6; k++) { e[k] = src[lane + 32 * k]; s += e[k]; ss += e[k] * e[k]; }
#pragma unroll
    for (int o = 16; o > 0; o >>= 1) {
        s  += __shfl_xor_sync(0xffffffffu, s,  o);
        ss += __shfl_xor_sync(0xffffffffu, ss, o);
    }
    float mu = s * (1.f / Cc);
    float var = ss * (1.f / Cc) - mu * mu;
    float rs = rsqrtf(var + EPSc);
    __half* dst = out + (size_t)warp * Cc;
#pragma unroll
    for (int k = 0; k < 6; k++) {
        int c = lane + 32 * k;
        dst[c] = __float2half((e[k] - mu) * rs * g[c] + bta[c]);
    }
}

// ---------------- wmma HMMA GEMM, 2-stage cp.async pipeline ----------------
// Block: 256 threads = 8 warps. Tile 128x64. Warp tile 32x32 (2x2 wmma m16n16k16).
// BK = 32, double buffered. fp16 operands, fp32 accumulate.
// EPI 0: half out, no act (qkv). EPI 1: scatter + shortcut -> fp32 (proj).
// EPI 2: GELU -> half (fc1). EPI 3: residual add -> fp32 (fc2 -> d_out).
#define BKw 32
#define ASTR 40
#define BSTR 40
#define STG  72
#define A_STAGE_B (128 * ASTR * 2)     // 10240 bytes per stage
#define B_STAGE_B (64 * BSTR * 2)      // 5120 bytes per stage
#define B_BASE    (2 * A_STAGE_B)      // 20480
#define SMEM_AB   (B_BASE + 2 * B_STAGE_B)   // 30720
#define SMEM_STG  (128 * STG * 4)            // 36864
#define SMEM_TOT  (SMEM_STG > SMEM_AB ? SMEM_STG : SMEM_AB)

template<int EPI>
__global__ void __launch_bounds__(256) hgemm_kernel(const __half* __restrict__ A,
                                                    const __half* __restrict__ Bw,
                                                    const float* __restrict__ bias,
                                                    const float* __restrict__ add,
                                                    float* __restrict__ outF,
                                                    __half* __restrict__ outH,
                                                    int N, int K) {
    extern __shared__ char smem[];
    float* stage = (float*)smem;
    uint32_t sbase = smem_u32(smem);

    int tid = threadIdx.x;
    int wid = tid >> 5;
    int wr = wid & 3;
    int wc = wid >> 2;
    int row0 = blockIdx.y * 128;
    int col0 = blockIdx.x * 64;

    const __half* Ab = A  + (size_t)row0 * K;
    const __half* Bb = Bw + (size_t)col0 * K;

    wmma::fragment<wmma::accumulator, 16, 16, 16, float> cf[2][2];
#pragma unroll
    for (int i = 0; i < 2; i++)
#pragma unroll
        for (int j = 0; j < 2; j++)
            wmma::fill_fragment(cf[i][j], 0.0f);

    // async-load one BK chunk into stage s
    int lar = tid >> 1;                 // A row 0..127
    int las = (tid & 1) * 2;            // A seg 0 or 2 (of 4)
    int lbr = tid >> 2;                 // B row 0..63
    int lbs = tid & 3;                  // B seg
    int nch = K >> 5;

    {
        // chunk 0 -> stage 0
        const __half* ga = Ab + (size_t)lar * K + las * 8;
        uint32_t sa = sbase + (uint32_t)(lar * 80 + las * 16);
        cp_async16(sa, ga);
        cp_async16(sa + 16, ga + 8);
        cp_async16(sbase + B_BASE + (uint32_t)(lbr * 80 + lbs * 16),
                   Bb + (size_t)lbr * K + lbs * 8);
        CP_COMMIT();
    }

    for (int c = 0; c < nch; c++) {
        int s = c & 1;
        if (c + 1 < nch) {
            int sn = (c + 1) & 1;
            int k0 = (c + 1) << 5;
            const __half* ga = Ab + (size_t)lar * K + k0 + las * 8;
            uint32_t sa = sbase + (uint32_t)(sn * A_STAGE_B + lar * 80 + las * 16);
            cp_async16(sa, ga);
            cp_async16(sa + 16, ga + 8);
            cp_async16(sbase + (uint32_t)(B_BASE + sn * B_STAGE_B + lbr * 80 + lbs * 16),
                       Bb + (size_t)lbr * K + k0 + lbs * 8);
            CP_COMMIT();
            CP_WAIT1();
        } else {
            CP_WAIT0();
        }
        __syncthreads();

        const __half* As = (const __half*)smem + s * (A_STAGE_B / 2);
        const __half* Bs = (const __half*)(smem + B_BASE) + s * (B_STAGE_B / 2);
#pragma unroll
        for (int ks = 0; ks < 2; ks++) {
            wmma::fragment<wmma::matrix_a, 16, 16, 16, __half, wmma::row_major> af[2];
            wmma::fragment<wmma::matrix_b, 16, 16, 16, __half, wmma::col_major> bf[2];
#pragma unroll
            for (int i = 0; i < 2; i++)
                wmma::load_matrix_sync(af[i], As + (wr * 32 + i * 16) * ASTR + ks * 16, ASTR);
#pragma unroll
            for (int j = 0; j < 2; j++)
                wmma::load_matrix_sync(bf[j], Bs + (wc * 32 + j * 16) * BSTR + ks * 16, BSTR);
#pragma unroll
            for (int i = 0; i < 2; i++)
#pragma unroll
                for (int j = 0; j < 2; j++)
                    wmma::mma_sync(cf[i][j], af[i], bf[j], cf[i][j]);
        }
        __syncthreads();   // protect stage s before it is refilled next+1 iteration
    }

    // stage accumulators to smem (fp32), fused coalesced epilogue
#pragma unroll
    for (int i = 0; i < 2; i++)
#pragma unroll
        for (int j = 0; j < 2; j++)
            wmma::store_matrix_sync(stage + (wr * 32 + i * 16) * STG + wc * 32 + j * 16,
                                    cf[i][j], STG, wmma::mem_row_major);
    __syncthreads();

    for (int idx = tid; idx < 128 * 16; idx += 256) {
        int rr = idx >> 4, v = idx & 15;
        float4 val = *(float4*)&stage[rr * STG + 4 * v];
        int m  = row0 + rr;
        int c0 = col0 + 4 * v;
        float4 b4 = *(const float4*)&bias[c0];
        val.x += b4.x; val.y += b4.y; val.z += b4.z; val.w += b4.w;
        if (EPI == 0) {
            __half2 h0 = __floats2half2_rn(val.x, val.y);
            __half2 h1 = __floats2half2_rn(val.z, val.w);
            uint2 pk; pk.x = *(uint32_t*)&h0; pk.y = *(uint32_t*)&h1;
            *(uint2*)&outH[(size_t)m * N + c0] = pk;
        } else if (EPI == 1) {
            int b; int tok = win_to_token(m, b);
            size_t base = ((size_t)b * (Hc * Wc) + tok) * Cc + c0;
            float4 a4 = *(const float4*)&add[base];
            val.x += a4.x; val.y += a4.y; val.z += a4.z; val.w += a4.w;
            *(float4*)&outF[base] = val;
        } else if (EPI == 2) {
            const float inv_s2 = 0.70710678118654752f;
            val.x = 0.5f * val.x * (1.0f + erff(val.x * inv_s2));
            val.y = 0.5f * val.y * (1.0f + erff(val.y * inv_s2));
            val.z = 0.5f * val.z * (1.0f + erff(val.z * inv_s2));
            val.w = 0.5f * val.w * (1.0f + erff(val.w * inv_s2));
            __half2 h0 = __floats2half2_rn(val.x, val.y);
            __half2 h1 = __floats2half2_rn(val.z, val.w);
            uint2 pk; pk.x = *(uint32_t*)&h0; pk.y = *(uint32_t*)&h1;
            *(uint2*)&outH[(size_t)m * N + c0] = pk;
        } else {  // EPI 3
            size_t base = (size_t)m * Cc + c0;
            float4 a4 = *(const float4*)&add[base];
            val.x += a4.x; val.y += a4.y; val.z += a4.z; val.w += a4.w;
            *(float4*)&outF[base] = val;
        }
    }
}

// ---------------- attention: one block per (window, head), fp16 qkv in ----------------
__global__ void __launch_bounds__(256) attn_kernel(const __half* __restrict__ qkv,
                                                   const float* __restrict__ rpb,
                                                   __half* __restrict__ out) {
    int bh = blockIdx.x;
    int b_ = bh / NHc;
    int h  = bh - b_ * NHc;
    int tid = threadIdx.x;

    __shared__ float qs[Nc * HDc];
    __shared__ float ks[Nc * HDc];
    __shared__ float vs[Nc * HDc];
    __shared__ float S[Nc * 50];

    for (int idx = tid; idx < Nc * HDc; idx += 256) {
        int n = idx >> 5, d = idx & 31;
        size_t rb = ((size_t)b_ * Nc + n) * (3 * Cc) + h * HDc + d;
        qs[idx] = __half2float(qkv[rb]) * SCALEc;
        ks[idx] = __half2float(qkv[rb + Cc]);
        vs[idx] = __half2float(qkv[rb + 2 * Cc]);
    }
    __syncthreads();

    int wi = b_ & 63;
    int wr = wi >> 3, wc = wi & 7;
    for (int idx = tid; idx < Nc * Nc; idx += 256) {
        int i = idx / Nc, j = idx - i * Nc;
        float s = 0.f;
        const float* qi = qs + i * HDc;
        const float* kj = ks + j * HDc;
#pragma unroll
        for (int d = 0; d < HDc; d++) s += qi[d] * kj[d];
        int ri = i / WSc, ci = i % WSc;
        int rj = j / WSc, cj = j % WSc;
        int rel = (ri - rj + WSc - 1) * (2 * WSc - 1) + (ci - cj + WSc - 1);
        s += rpb[rel * NHc + h];
        int cnti = regionOf(wr * WSc + ri) * 3 + regionOf(wc * WSc + ci);
        int cntj = regionOf(wr * WSc + rj) * 3 + regionOf(wc * WSc + cj);
        if (cnti != cntj) s -= 100.0f;
        S[i * 50 + j] = s;
    }
    __syncthreads();

    int w = tid >> 5, lane = tid & 31;
    for (int i = w; i < Nc; i += 8) {
        float* row = S + i * 50;
        float mx = -1e30f;
        for (int j = lane; j < Nc; j += 32) mx = fmaxf(mx, row[j]);
#pragma unroll
        for (int o = 16; o > 0; o >>= 1) mx = fmaxf(mx, __shfl_xor_sync(0xffffffffu, mx, o));
        float sum = 0.f;
        for (int j = lane; j < Nc; j += 32) {
            float e = __expf(row[j] - mx);
            row[j] = e;
            sum += e;
        }
#pragma unroll
        for (int o = 16; o > 0; o >>= 1) sum += __shfl_xor_sync(0xffffffffu, sum, o);
        float inv = 1.0f / sum;
        for (int j = lane; j < Nc; j += 32) row[j] *= inv;
    }
    __syncthreads();

    for (int idx = tid; idx < Nc * HDc; idx += 256) {
        int i = idx >> 5, d = idx & 31;
        const float* row = S + i * 50;
        float s = 0.f;
#pragma unroll
        for (int j = 0; j < Nc; j++) s += row[j] * vs[j * HDc + d];
        out[((size_t)b_ * Nc + i) * Cc + h * HDc + d] = __float2half(s);
    }
}

// ---------------- launch ----------------
extern "C" void kernel_launch(void* const* d_in, const int* in_sizes, int n_in,
                              void* d_out, int out_size) {
    const float* x       = (const float*)d_in[0];
    const float* norm1_g = (const float*)d_in[1];
    const float* norm1_b = (const float*)d_in[2];
    const float* qkv_w   = (const float*)d_in[3];
    const float* qkv_b   = (const float*)d_in[4];
    const float* proj_w  = (const float*)d_in[5];
    const float* proj_b  = (const float*)d_in[6];
    const float* rpb     = (const float*)d_in[7];
    const float* norm2_g = (const float*)d_in[8];
    const float* norm2_b = (const float*)d_in[9];
    const float* fc1_w   = (const float*)d_in[10];
    const float* fc1_b   = (const float*)d_in[11];
    const float* fc2_w   = (const float*)d_in[12];
    const float* fc2_b   = (const float*)d_in[13];
    float* outp = (float*)d_out;

    __half *p_xw, *p_qkv, *p_attn, *p_ln2, *p_fc1, *p_wqkv, *p_wproj, *p_wfc1, *p_wfc2;
    float *p_h;
    cudaGetSymbolAddress((void**)&p_xw,   g_xw_h);
    cudaGetSymbolAddress((void**)&p_qkv,  g_qkv_h);
    cudaGetSymbolAddress((void**)&p_attn, g_attn_h);
    cudaGetSymbolAddress((void**)&p_h,    g_h);
    cudaGetSymbolAddress((void**)&p_ln2,  g_ln2_h);
    cudaGetSymbolAddress((void**)&p_fc1,  g_fc1_h);
    cudaGetSymbolAddress((void**)&p_wqkv, g_wqkv_h);
    cudaGetSymbolAddress((void**)&p_wproj,g_wproj_h);
    cudaGetSymbolAddress((void**)&p_wfc1, g_wfc1_h);
    cudaGetSymbolAddress((void**)&p_wfc2, g_wfc2_h);

    // one fused weight conversion
    const int ntotW = NQKV + NPRJ + NFC1 + NFC2;
    f2h4_kernel<<<(ntotW + 255) / 256, 256>>>(qkv_w, proj_w, fc1_w, fc2_w,
                                              p_wqkv, p_wproj, p_wfc1, p_wfc2);

    const int lnBlocks = (Mrows * 32 + 255) / 256;
    const int smemB = SMEM_TOT;

    // 1) LN1 + shift + window partition (-> fp16)
    ln_kernel<0><<<lnBlocks, 256>>>(x, norm1_g, norm1_b, p_xw);

    // 2) QKV GEMM (HMMA, pipelined) -> fp16
    hgemm_kernel<0><<<dim3(9, 784), 256, smemB>>>(p_xw, p_wqkv, qkv_b, nullptr,
                                                  nullptr, p_qkv, 3*Cc, Cc);

    // 3) windowed attention (fp16 in, fp16 out)
    attn_kernel<<<Bc * NWIN * NHc, 256>>>(p_qkv, rpb, p_attn);

    // 4) proj GEMM + window reverse + roll + shortcut -> fp32 h
    hgemm_kernel<1><<<dim3(3, 784), 256, smemB>>>(p_attn, p_wproj, proj_b, x,
                                                  p_h, nullptr, Cc, Cc);

    // 5) LN2 (-> fp16)
    ln_kernel<1><<<lnBlocks, 256>>>(p_h, norm2_g, norm2_b, p_ln2);

    // 6) FC1 + GELU (-> fp16)
    hgemm_kernel<2><<<dim3(12, 784), 256, smemB>>>(p_ln2, p_wfc1, fc1_b, nullptr,
                                                   nullptr, p_fc1, HIDc, Cc);

    // 7) FC2 + residual -> fp32 out
    hgemm_kernel<3><<<dim3(3, 784), 256, smemB>>>(p_fc1, p_wfc2, fc2_b, p_h,
                                                  outp, nullptr, Cc, HIDc);
}

// round 10
// speedup vs baseline: 5.2149x; 2.2920x over previous
#include <cuda_runtime.h>
#include <cuda_fp16.h>
#include <mma.h>
#include <math.h>
#include <stdint.h>

using namespace nvcuda;

// ---------------- problem constants ----------------
#define Bc   32
#define Hc   56
#define Wc   56
#define Cc   192
#define WSc  7
#define SSc  3
#define NHc  6
#define Nc   49
#define HDc  32
#define HIDc 768
#define NWIN 64
#define Mrows (Bc * Hc * Wc)   // 100352
#define SCALEc 0.17677669529663687f
#define EPSc 1e-5f

// ---------------- scratch (device globals, no allocs) ----------------
__device__ __half g_xw_h  [(size_t)Mrows * Cc];
__device__ __half g_qkv_h [(size_t)Mrows * 3 * Cc];
__device__ __half g_attn_h[(size_t)Mrows * Cc];
__device__ float  g_h     [(size_t)Mrows * Cc];
__device__ __half g_ln2_h [(size_t)Mrows * Cc];
__device__ __half g_fc1_h [(size_t)Mrows * HIDc];
__device__ __half g_wqkv_h[3 * Cc * Cc];
__device__ __half g_wproj_h[Cc * Cc];
__device__ __half g_wfc1_h[HIDc * Cc];
__device__ __half g_wfc2_h[Cc * HIDc];

// ---------------- index helpers ----------------
__device__ __forceinline__ int win_to_token(int r, int& b) {
    int b_ = r / Nc;
    int n  = r - b_ * Nc;
    b = b_ >> 6;
    int wi = b_ & 63;
    int wr = wi >> 3, wc = wi & 7;
    int hs = wr * WSc + n / WSc;
    int ws = wc * WSc + n % WSc;
    int ho = hs + SSc; if (ho >= Hc) ho -= Hc;
    int wo = ws + SSc; if (wo >= Wc) wo -= Wc;
    return ho * Wc + wo;
}
__device__ __forceinline__ int regionOf(int p) {
    return (p < Hc - WSc) ? 0 : ((p < Hc - SSc) ? 1 : 2);
}

__device__ __forceinline__ uint32_t smem_u32(const void* p) {
    uint32_t a;
    asm("{ .reg .u64 t; cvta.to.shared.u64 t, %1; cvt.u32.u64 %0, t; }" : "=r"(a) : "l"(p));
    return a;
}
__device__ __forceinline__ void cp_async16(uint32_t saddr, const void* g) {
    asm volatile("cp.async.cg.shared.global [%0], [%1], 16;" :: "r"(saddr), "l"(g));
}
#define CP_COMMIT() asm volatile("cp.async.commit_group;" ::: "memory")
#define CP_WAIT1()  asm volatile("cp.async.wait_group 1;" ::: "memory")
#define CP_WAIT0()  asm volatile("cp.async.wait_group 0;" ::: "memory")

// ---------------- fused weight conversion ----------------
#define NQKV (3 * Cc * Cc)
#define NPRJ (Cc * Cc)
#define NFC1 (HIDc * Cc)
#define NFC2 (Cc * HIDc)
__global__ void __launch_bounds__(256) f2h4_kernel(const float* __restrict__ w0,
                                                   const float* __restrict__ w1,
                                                   const float* __restrict__ w2,
                                                   const float* __restrict__ w3,
                                                   __half* __restrict__ o0,
                                                   __half* __restrict__ o1,
                                                   __half* __restrict__ o2,
                                                   __half* __restrict__ o3) {
    int i = blockIdx.x * blockDim.x + threadIdx.x;
    if (i < NQKV) o0[i] = __float2half(w0[i]);
    int j = i - NQKV;
    if (j >= 0 && j < NPRJ) o1[j] = __float2half(w1[j]);
    int k = j - NPRJ;
    if (k >= 0 && k < NFC1) o2[k] = __float2half(w2[k]);
    int l = k - NFC1;
    if (l >= 0 && l < NFC2) o3[l] = __float2half(w3[l]);
}

// ---------------- LayerNorm kernels (warp per row), output fp16 ----------------
template<int MODE>
__global__ void __launch_bounds__(256) ln_kernel(const float* __restrict__ x,
                                                 const float* __restrict__ g,
                                                 const float* __restrict__ bta,
                                                 __half* __restrict__ out) {
    int warp = (blockIdx.x * blockDim.x + threadIdx.x) >> 5;
    int lane = threadIdx.x & 31;
    if (warp >= Mrows) return;
    const float* src;
    if (MODE == 0) {
        int b; int tok = win_to_token(warp, b);
        src = x + ((size_t)b * (Hc * Wc) + tok) * Cc;
    } else {
        src = x + (size_t)warp * Cc;
    }
    float e[6]; float s = 0.f, ss = 0.f;
#pragma unroll
    for (int k = 0; k < 6; k++) { e[k] = src[lane + 32 * k]; s += e[k]; ss += e[k] * e[k]; }
#pragma unroll
    for (int o = 16; o > 0; o >>= 1) {
        s  += __shfl_xor_sync(0xffffffffu, s,  o);
        ss += __shfl_xor_sync(0xffffffffu, ss, o);
    }
    float mu = s * (1.f / Cc);
    float var = ss * (1.f / Cc) - mu * mu;
    float rs = rsqrtf(var + EPSc);
    __half* dst = out + (size_t)warp * Cc;
#pragma unroll
    for (int k = 0; k < 6; k++) {
        int c = lane + 32 * k;
        dst[c] = __float2half((e[k] - mu) * rs * g[c] + bta[c]);
    }
}

// ---------------- wmma HMMA GEMM, 2-stage cp.async pipeline ----------------
#define BKw 32
#define ASTR 40
#define BSTR 40
#define STG  72
#define A_STAGE_B (128 * ASTR * 2)
#define B_STAGE_B (64 * BSTR * 2)
#define B_BASE    (2 * A_STAGE_B)
#define SMEM_AB   (B_BASE + 2 * B_STAGE_B)
#define SMEM_STG  (128 * STG * 4)
#define SMEM_TOT  (SMEM_STG > SMEM_AB ? SMEM_STG : SMEM_AB)

template<int EPI>
__global__ void __launch_bounds__(256) hgemm_kernel(const __half* __restrict__ A,
                                                    const __half* __restrict__ Bw,
                                                    const float* __restrict__ bias,
                                                    const float* __restrict__ add,
                                                    float* __restrict__ outF,
                                                    __half* __restrict__ outH,
                                                    int N, int K) {
    extern __shared__ char smem[];
    float* stage = (float*)smem;
    uint32_t sbase = smem_u32(smem);

    int tid = threadIdx.x;
    int wid = tid >> 5;
    int wr = wid & 3;
    int wc = wid >> 2;
    int row0 = blockIdx.y * 128;
    int col0 = blockIdx.x * 64;

    const __half* Ab = A  + (size_t)row0 * K;
    const __half* Bb = Bw + (size_t)col0 * K;

    wmma::fragment<wmma::accumulator, 16, 16, 16, float> cf[2][2];
#pragma unroll
    for (int i = 0; i < 2; i++)
#pragma unroll
        for (int j = 0; j < 2; j++)
            wmma::fill_fragment(cf[i][j], 0.0f);

    int lar = tid >> 1;
    int las = (tid & 1) * 2;
    int lbr = tid >> 2;
    int lbs = tid & 3;
    int nch = K >> 5;

    {
        const __half* ga = Ab + (size_t)lar * K + las * 8;
        uint32_t sa = sbase + (uint32_t)(lar * 80 + las * 16);
        cp_async16(sa, ga);
        cp_async16(sa + 16, ga + 8);
        cp_async16(sbase + B_BASE + (uint32_t)(lbr * 80 + lbs * 16),
                   Bb + (size_t)lbr * K + lbs * 8);
        CP_COMMIT();
    }

    for (int c = 0; c < nch; c++) {
        int s = c & 1;
        if (c + 1 < nch) {
            int sn = (c + 1) & 1;
            int k0 = (c + 1) << 5;
            const __half* ga = Ab + (size_t)lar * K + k0 + las * 8;
            uint32_t sa = sbase + (uint32_t)(sn * A_STAGE_B + lar * 80 + las * 16);
            cp_async16(sa, ga);
            cp_async16(sa + 16, ga + 8);
            cp_async16(sbase + (uint32_t)(B_BASE + sn * B_STAGE_B + lbr * 80 + lbs * 16),
                       Bb + (size_t)lbr * K + k0 + lbs * 8);
            CP_COMMIT();
            CP_WAIT1();
        } else {
            CP_WAIT0();
        }
        __syncthreads();

        const __half* As = (const __half*)smem + s * (A_STAGE_B / 2);
        const __half* Bs = (const __half*)(smem + B_BASE) + s * (B_STAGE_B / 2);
#pragma unroll
        for (int ks = 0; ks < 2; ks++) {
            wmma::fragment<wmma::matrix_a, 16, 16, 16, __half, wmma::row_major> af[2];
            wmma::fragment<wmma::matrix_b, 16, 16, 16, __half, wmma::col_major> bf[2];
#pragma unroll
            for (int i = 0; i < 2; i++)
                wmma::load_matrix_sync(af[i], As + (wr * 32 + i * 16) * ASTR + ks * 16, ASTR);
#pragma unroll
            for (int j = 0; j < 2; j++)
                wmma::load_matrix_sync(bf[j], Bs + (wc * 32 + j * 16) * BSTR + ks * 16, BSTR);
#pragma unroll
            for (int i = 0; i < 2; i++)
#pragma unroll
                for (int j = 0; j < 2; j++)
                    wmma::mma_sync(cf[i][j], af[i], bf[j], cf[i][j]);
        }
        __syncthreads();
    }

#pragma unroll
    for (int i = 0; i < 2; i++)
#pragma unroll
        for (int j = 0; j < 2; j++)
            wmma::store_matrix_sync(stage + (wr * 32 + i * 16) * STG + wc * 32 + j * 16,
                                    cf[i][j], STG, wmma::mem_row_major);
    __syncthreads();

    for (int idx = tid; idx < 128 * 16; idx += 256) {
        int rr = idx >> 4, v = idx & 15;
        float4 val = *(float4*)&stage[rr * STG + 4 * v];
        int m  = row0 + rr;
        int c0 = col0 + 4 * v;
        float4 b4 = *(const float4*)&bias[c0];
        val.x += b4.x; val.y += b4.y; val.z += b4.z; val.w += b4.w;
        if (EPI == 0) {
            __half2 h0 = __floats2half2_rn(val.x, val.y);
            __half2 h1 = __floats2half2_rn(val.z, val.w);
            uint2 pk; pk.x = *(uint32_t*)&h0; pk.y = *(uint32_t*)&h1;
            *(uint2*)&outH[(size_t)m * N + c0] = pk;
        } else if (EPI == 1) {
            int b; int tok = win_to_token(m, b);
            size_t base = ((size_t)b * (Hc * Wc) + tok) * Cc + c0;
            float4 a4 = *(const float4*)&add[base];
            val.x += a4.x; val.y += a4.y; val.z += a4.z; val.w += a4.w;
            *(float4*)&outF[base] = val;
        } else if (EPI == 2) {
            const float inv_s2 = 0.70710678118654752f;
            val.x = 0.5f * val.x * (1.0f + erff(val.x * inv_s2));
            val.y = 0.5f * val.y * (1.0f + erff(val.y * inv_s2));
            val.z = 0.5f * val.z * (1.0f + erff(val.z * inv_s2));
            val.w = 0.5f * val.w * (1.0f + erff(val.w * inv_s2));
            __half2 h0 = __floats2half2_rn(val.x, val.y);
            __half2 h1 = __floats2half2_rn(val.z, val.w);
            uint2 pk; pk.x = *(uint32_t*)&h0; pk.y = *(uint32_t*)&h1;
            *(uint2*)&outH[(size_t)m * N + c0] = pk;
        } else {
            size_t base = (size_t)m * Cc + c0;
            float4 a4 = *(const float4*)&add[base];
            val.x += a4.x; val.y += a4.y; val.z += a4.z; val.w += a4.w;
            *(float4*)&outF[base] = val;
        }
    }
}

// ---------------- attention (wmma HMMA, 49 padded to 64) ----------------
// One block per (window, head). 256 threads = 8 warps.
// S = Q@K^T : 4x4 m16n16k16 tiles (2 per warp), fp32 accum.
// softmax fp32 with on-the-fly rpb bias + shift mask; P stored fp16 (padded cols zeroed).
// out = P@V : 4x2 tiles (1 per warp).
#define QSTR 40     // halves
#define SSTR 72     // S: floats / P: halves stride
#define PVSTR 40    // PV stage stride (floats)

__global__ void __launch_bounds__(256) attn_kernel(const __half* __restrict__ qkv,
                                                   const float* __restrict__ rpb,
                                                   __half* __restrict__ out) {
    int bh = blockIdx.x;
    int b_ = bh / NHc;
    int h  = bh - b_ * NHc;
    int tid = threadIdx.x;
    int wid = tid >> 5, lane = tid & 31;

    __shared__ __half Qs[64 * QSTR];
    __shared__ __half Ks[64 * QSTR];
    __shared__ __half Vs[64 * QSTR];
    __shared__ float  Sf[64 * SSTR];     // also reused (prefix) as PV fp32 stage
    __shared__ __half Ph[64 * SSTR];

    // ---- load Q,K,V: one uint4 (8 halves) per thread per tensor ----
    {
        int r = tid >> 2, seg = tid & 3;     // 64 rows x 4 segs
        uint4 zz = make_uint4(0, 0, 0, 0);
        if (r < Nc) {
            const __half* src = qkv + ((size_t)b_ * Nc + r) * (3 * Cc) + h * HDc + seg * 8;
            *(uint4*)(Qs + r * QSTR + seg * 8) = *(const uint4*)src;
            *(uint4*)(Ks + r * QSTR + seg * 8) = *(const uint4*)(src + Cc);
            *(uint4*)(Vs + r * QSTR + seg * 8) = *(const uint4*)(src + 2 * Cc);
        } else {
            *(uint4*)(Qs + r * QSTR + seg * 8) = zz;
            *(uint4*)(Ks + r * QSTR + seg * 8) = zz;
            *(uint4*)(Vs + r * QSTR + seg * 8) = zz;
        }
    }
    __syncthreads();

    // ---- S = Q @ K^T (16 tiles, 2 per warp) ----
#pragma unroll
    for (int t = wid * 2; t < wid * 2 + 2; t++) {
        int tr = t >> 2, tc = t & 3;
        wmma::fragment<wmma::accumulator, 16, 16, 16, float> c;
        wmma::fill_fragment(c, 0.0f);
#pragma unroll
        for (int kt = 0; kt < 2; kt++) {
            wmma::fragment<wmma::matrix_a, 16, 16, 16, __half, wmma::row_major> a;
            wmma::fragment<wmma::matrix_b, 16, 16, 16, __half, wmma::col_major> bfr;
            wmma::load_matrix_sync(a,   Qs + (tr * 16) * QSTR + kt * 16, QSTR);
            wmma::load_matrix_sync(bfr, Ks + (tc * 16) * QSTR + kt * 16, QSTR);
            wmma::mma_sync(c, a, bfr, c);
        }
        wmma::store_matrix_sync(Sf + (tr * 16) * SSTR + tc * 16, c, SSTR, wmma::mem_row_major);
    }
    __syncthreads();

    // ---- softmax rows (fp32), bias + mask on the fly, write P fp16 ----
    int wi = b_ & 63;
    int wrw = wi >> 3, wcw = wi & 7;
    for (int i = wid; i < Nc; i += 8) {
        int ri = i / WSc, ci = i % WSc;
        int regi = regionOf(wrw * WSc + ri) * 3 + regionOf(wcw * WSc + ci);
        float* row = Sf + i * SSTR;

        // element 1: j = lane ; element 2: j = lane + 32
        float v1 = -1e30f, v2 = -1e30f;
        int j1 = lane, j2 = lane + 32;
        if (j1 < Nc) {
            int rj = j1 / WSc, cj = j1 % WSc;
            int rel = (ri - rj + WSc - 1) * (2 * WSc - 1) + (ci - cj + WSc - 1);
            v1 = row[j1] * SCALEc + rpb[rel * NHc + h];
            int regj = regionOf(wrw * WSc + rj) * 3 + regionOf(wcw * WSc + cj);
            if (regi != regj) v1 -= 100.0f;
        }
        if (j2 < Nc) {
            int rj = j2 / WSc, cj = j2 % WSc;
            int rel = (ri - rj + WSc - 1) * (2 * WSc - 1) + (ci - cj + WSc - 1);
            v2 = row[j2] * SCALEc + rpb[rel * NHc + h];
            int regj = regionOf(wrw * WSc + rj) * 3 + regionOf(wcw * WSc + cj);
            if (regi != regj) v2 -= 100.0f;
        }
        float mx = fmaxf(v1, v2);
#pragma unroll
        for (int o = 16; o > 0; o >>= 1) mx = fmaxf(mx, __shfl_xor_sync(0xffffffffu, mx, o));
        float e1 = (j1 < Nc) ? __expf(v1 - mx) : 0.f;
        float e2 = (j2 < Nc) ? __expf(v2 - mx) : 0.f;
        float sum = e1 + e2;
#pragma unroll
        for (int o = 16; o > 0; o >>= 1) sum += __shfl_xor_sync(0xffffffffu, sum, o);
        float inv = 1.0f / sum;
        __half* prow = Ph + i * SSTR;
        prow[j1] = __float2half(e1 * inv);
        prow[j2] = __float2half(e2 * inv);
    }
    // zero padded rows of P (rows 49..63) so no NaNs leak via uninitialized smem
    for (int idx = tid; idx < (64 - Nc) * 64; idx += 256) {
        int r = Nc + (idx >> 6), j = idx & 63;
        Ph[r * SSTR + j] = __float2half(0.f);
    }
    __syncthreads();

    // ---- out = P @ V (8 tiles, 1 per warp) ----
    {
        int tr = wid >> 1, tc = wid & 1;
        wmma::fragment<wmma::accumulator, 16, 16, 16, float> c;
        wmma::fill_fragment(c, 0.0f);
#pragma unroll
        for (int kt = 0; kt < 4; kt++) {
            wmma::fragment<wmma::matrix_a, 16, 16, 16, __half, wmma::row_major> a;
            wmma::fragment<wmma::matrix_b, 16, 16, 16, __half, wmma::row_major> bfr;
            wmma::load_matrix_sync(a,   Ph + (tr * 16) * SSTR + kt * 16, SSTR);
            wmma::load_matrix_sync(bfr, Vs + (kt * 16) * QSTR + tc * 16, QSTR);
            wmma::mma_sync(c, a, bfr, c);
        }
        __syncthreads();   // Sf reuse: S-phase reads done
        wmma::store_matrix_sync(Sf + (tr * 16) * PVSTR + tc * 16, c, PVSTR, wmma::mem_row_major);
    }
    __syncthreads();

    // ---- store out rows < 49 ----
    for (int idx = tid; idx < Nc * HDc; idx += 256) {
        int i = idx >> 5, d = idx & 31;
        out[((size_t)b_ * Nc + i) * Cc + h * HDc + d] = __float2half(Sf[i * PVSTR + d]);
    }
}

// ---------------- launch ----------------
extern "C" void kernel_launch(void* const* d_in, const int* in_sizes, int n_in,
                              void* d_out, int out_size) {
    const float* x       = (const float*)d_in[0];
    const float* norm1_g = (const float*)d_in[1];
    const float* norm1_b = (const float*)d_in[2];
    const float* qkv_w   = (const float*)d_in[3];
    const float* qkv_b   = (const float*)d_in[4];
    const float* proj_w  = (const float*)d_in[5];
    const float* proj_b  = (const float*)d_in[6];
    const float* rpb     = (const float*)d_in[7];
    const float* norm2_g = (const float*)d_in[8];
    const float* norm2_b = (const float*)d_in[9];
    const float* fc1_w   = (const float*)d_in[10];
    const float* fc1_b   = (const float*)d_in[11];
    const float* fc2_w   = (const float*)d_in[12];
    const float* fc2_b   = (const float*)d_in[13];
    float* outp = (float*)d_out;

    __half *p_xw, *p_qkv, *p_attn, *p_ln2, *p_fc1, *p_wqkv, *p_wproj, *p_wfc1, *p_wfc2;
    float *p_h;
    cudaGetSymbolAddress((void**)&p_xw,   g_xw_h);
    cudaGetSymbolAddress((void**)&p_qkv,  g_qkv_h);
    cudaGetSymbolAddress((void**)&p_attn, g_attn_h);
    cudaGetSymbolAddress((void**)&p_h,    g_h);
    cudaGetSymbolAddress((void**)&p_ln2,  g_ln2_h);
    cudaGetSymbolAddress((void**)&p_fc1,  g_fc1_h);
    cudaGetSymbolAddress((void**)&p_wqkv, g_wqkv_h);
    cudaGetSymbolAddress((void**)&p_wproj,g_wproj_h);
    cudaGetSymbolAddress((void**)&p_wfc1, g_wfc1_h);
    cudaGetSymbolAddress((void**)&p_wfc2, g_wfc2_h);

    const int ntotW = NQKV + NPRJ + NFC1 + NFC2;
    f2h4_kernel<<<(ntotW + 255) / 256, 256>>>(qkv_w, proj_w, fc1_w, fc2_w,
                                              p_wqkv, p_wproj, p_wfc1, p_wfc2);

    const int lnBlocks = (Mrows * 32 + 255) / 256;
    const int smemB = SMEM_TOT;

    // 1) LN1 + shift + window partition (-> fp16)
    ln_kernel<0><<<lnBlocks, 256>>>(x, norm1_g, norm1_b, p_xw);

    // 2) QKV GEMM (HMMA, pipelined) -> fp16
    hgemm_kernel<0><<<dim3(9, 784), 256, smemB>>>(p_xw, p_wqkv, qkv_b, nullptr,
                                                  nullptr, p_qkv, 3*Cc, Cc);

    // 3) windowed attention (wmma)
    attn_kernel<<<Bc * NWIN * NHc, 256>>>(p_qkv, rpb, p_attn);

    // 4) proj GEMM + window reverse + roll + shortcut -> fp32 h
    hgemm_kernel<1><<<dim3(3, 784), 256, smemB>>>(p_attn, p_wproj, proj_b, x,
                                                  p_h, nullptr, Cc, Cc);

    // 5) LN2 (-> fp16)
    ln_kernel<1><<<lnBlocks, 256>>>(p_h, norm2_g, norm2_b, p_ln2);

    // 6) FC1 + GELU (-> fp16)
    hgemm_kernel<2><<<dim3(12, 784), 256, smemB>>>(p_ln2, p_wfc1, fc1_b, nullptr,
                                                   nullptr, p_fc1, HIDc, Cc);

    // 7) FC2 + residual -> fp32 out
    hgemm_kernel<3><<<dim3(3, 784), 256, smemB>>>(p_fc1, p_wfc2, fc2_b, p_h,
                                                  outp, nullptr, Cc, HIDc);
}

// round 13
// speedup vs baseline: 5.2517x; 1.0071x over previous
#include <cuda_runtime.h>
#include <cuda_fp16.h>
#include <mma.h>
#include <math.h>
#include <stdint.h>

using namespace nvcuda;

// ---------------- problem constants ----------------
#define Bc   32
#define Hc   56
#define Wc   56
#define Cc   192
#define WSc  7
#define SSc  3
#define NHc  6
#define Nc   49
#define HDc  32
#define HIDc 768
#define NWIN 64
#define Mrows (Bc * Hc * Wc)   // 100352
#define SCALEc 0.17677669529663687f
#define EPSc 1e-5f

// ---------------- scratch (device globals, no allocs) ----------------
__device__ __half g_xw_h  [(size_t)Mrows * Cc];
__device__ __half g_qkv_h [(size_t)Mrows * 3 * Cc];
__device__ __half g_attn_h[(size_t)Mrows * Cc];
__device__ float  g_h     [(size_t)Mrows * Cc];
__device__ __half g_ln2_h [(size_t)Mrows * Cc];
__device__ __half g_fc1_h [(size_t)Mrows * HIDc];
__device__ __half g_wqkv_h[3 * Cc * Cc];
__device__ __half g_wproj_h[Cc * Cc];
__device__ __half g_wfc1_h[HIDc * Cc];
__device__ __half g_wfc2_h[Cc * HIDc];
__device__ float  g_bm    [4 * NHc * Nc * Nc];   // combined bias+mask per window-type

// ---------------- index helpers ----------------
__device__ __forceinline__ int win_to_token(int r, int& b) {
    int b_ = r / Nc;
    int n  = r - b_ * Nc;
    b = b_ >> 6;
    int wi = b_ & 63;
    int wr = wi >> 3, wc = wi & 7;
    int hs = wr * WSc + n / WSc;
    int ws = wc * WSc + n % WSc;
    int ho = hs + SSc; if (ho >= Hc) ho -= Hc;
    int wo = ws + SSc; if (wo >= Wc) wo -= Wc;
    return ho * Wc + wo;
}
__device__ __forceinline__ int regionOf(int p) {
    return (p < Hc - WSc) ? 0 : ((p < Hc - SSc) ? 1 : 2);
}

__device__ __forceinline__ uint32_t smem_u32(const void* p) {
    uint32_t a;
    asm("{ .reg .u64 t; cvta.to.shared.u64 t, %1; cvt.u32.u64 %0, t; }" : "=r"(a) : "l"(p));
    return a;
}
__device__ __forceinline__ void cp_async16(uint32_t saddr, const void* g) {
    asm volatile("cp.async.cg.shared.global [%0], [%1], 16;" :: "r"(saddr), "l"(g));
}
#define CP_COMMIT() asm volatile("cp.async.commit_group;" ::: "memory")
#define CP_WAIT1()  asm volatile("cp.async.wait_group 1;" ::: "memory")
#define CP_WAIT0()  asm volatile("cp.async.wait_group 0;" ::: "memory")

// ---------------- precompute combined bias+mask table ----------------
// wt bit0: window row == 7 (bottom edge); bit1: window col == 7 (right edge)
#define NBM (4 * NHc * Nc * Nc)
__global__ void __launch_bounds__(256) bm_kernel(const float* __restrict__ rpb,
                                                 float* __restrict__ bm) {
    int idx = blockIdx.x * blockDim.x + threadIdx.x;
    if (idx >= NBM) return;
    int j = idx % Nc;
    int t = idx / Nc;
    int i = t % Nc;  t /= Nc;
    int h = t % NHc;
    int wt = t / NHc;
    int ri = i / WSc, ci = i % WSc;
    int rj = j / WSc, cj = j % WSc;
    int rel = (ri - rj + WSc - 1) * (2 * WSc - 1) + (ci - cj + WSc - 1);
    float v = rpb[rel * NHc + h];
    int regRi = (wt & 1) ? regionOf(49 + ri) : 0;
    int regCi = (wt & 2) ? regionOf(49 + ci) : 0;
    int regRj = (wt & 1) ? regionOf(49 + rj) : 0;
    int regCj = (wt & 2) ? regionOf(49 + cj) : 0;
    if (regRi * 3 + regCi != regRj * 3 + regCj) v -= 100.0f;
    bm[idx] = v;
}

// ---------------- fused weight conversion ----------------
#define NQKV (3 * Cc * Cc)
#define NPRJ (Cc * Cc)
#define NFC1 (HIDc * Cc)
#define NFC2 (Cc * HIDc)
__global__ void __launch_bounds__(256) f2h4_kernel(const float* __restrict__ w0,
                                                   const float* __restrict__ w1,
                                                   const float* __restrict__ w2,
                                                   const float* __restrict__ w3,
                                                   __half* __restrict__ o0,
                                                   __half* __restrict__ o1,
                                                   __half* __restrict__ o2,
                                                   __half* __restrict__ o3) {
    int i = blockIdx.x * blockDim.x + threadIdx.x;
    if (i < NQKV) o0[i] = __float2half(w0[i]);
    int j = i - NQKV;
    if (j >= 0 && j < NPRJ) o1[j] = __float2half(w1[j]);
    int k = j - NPRJ;
    if (k >= 0 && k < NFC1) o2[k] = __float2half(w2[k]);
    int l = k - NFC1;
    if (l >= 0 && l < NFC2) o3[l] = __float2half(w3[l]);
}

// ---------------- LayerNorm kernels (warp per row), output fp16 ----------------
template<int MODE>
__global__ void __launch_bounds__(256) ln_kernel(const float* __restrict__ x,
                                                 const float* __restrict__ g,
                                                 const float* __restrict__ bta,
                                                 __half* __restrict__ out) {
    int warp = (blockIdx.x * blockDim.x + threadIdx.x) >> 5;
    int lane = threadIdx.x & 31;
    if (warp >= Mrows) return;
    const float* src;
    if (MODE == 0) {
        int b; int tok = win_to_token(warp, b);
        src = x + ((size_t)b * (Hc * Wc) + tok) * Cc;
    } else {
        src = x + (size_t)warp * Cc;
    }
    float e[6]; float s = 0.f, ss = 0.f;
#pragma unroll
    for (int k = 0; k < 6; k++) { e[k] = src[lane + 32 * k]; s += e[k]; ss += e[k] * e[k]; }
#pragma unroll
    for (int o = 16; o > 0; o >>= 1) {
        s  += __shfl_xor_sync(0xffffffffu, s,  o);
        ss += __shfl_xor_sync(0xffffffffu, ss, o);
    }
    float mu = s * (1.f / Cc);
    float var = ss * (1.f / Cc) - mu * mu;
    float rs = rsqrtf(var + EPSc);
    __half* dst = out + (size_t)warp * Cc;
#pragma unroll
    for (int k = 0; k < 6; k++) {
        int c = lane + 32 * k;
        dst[c] = __float2half((e[k] - mu) * rs * g[c] + bta[c]);
    }
}

// ---------------- wmma HMMA GEMM, 2-stage cp.async pipeline ----------------
#define BKw 32
#define ASTR 40
#define BSTR 40
#define STG  72
#define A_STAGE_B (128 * ASTR * 2)
#define B_STAGE_B (64 * BSTR * 2)
#define B_BASE    (2 * A_STAGE_B)
#define SMEM_AB   (B_BASE + 2 * B_STAGE_B)
#define SMEM_STG  (128 * STG * 4)
#define SMEM_TOT  (SMEM_STG > SMEM_AB ? SMEM_STG : SMEM_AB)

// EPI 0: half out, q-columns pre-scaled by SCALE (qkv).
// EPI 1: scatter + shortcut -> fp32 (proj). EPI 2: GELU -> half (fc1).
// EPI 3: residual add -> fp32 (fc2 -> d_out).
template<int EPI>
__global__ void __launch_bounds__(256) hgemm_kernel(const __half* __restrict__ A,
                                                    const __half* __restrict__ Bw,
                                                    const float* __restrict__ bias,
                                                    const float* __restrict__ add,
                                                    float* __restrict__ outF,
                                                    __half* __restrict__ outH,
                                                    int N, int K) {
    extern __shared__ char smem[];
    float* stage = (float*)smem;
    uint32_t sbase = smem_u32(smem);

    int tid = threadIdx.x;
    int wid = tid >> 5;
    int wr = wid & 3;
    int wc = wid >> 2;
    int row0 = blockIdx.y * 128;
    int col0 = blockIdx.x * 64;

    const __half* Ab = A  + (size_t)row0 * K;
    const __half* Bb = Bw + (size_t)col0 * K;

    wmma::fragment<wmma::accumulator, 16, 16, 16, float> cf[2][2];
#pragma unroll
    for (int i = 0; i < 2; i++)
#pragma unroll
        for (int j = 0; j < 2; j++)
            wmma::fill_fragment(cf[i][j], 0.0f);

    int lar = tid >> 1;
    int las = (tid & 1) * 2;
    int lbr = tid >> 2;
    int lbs = tid & 3;
    int nch = K >> 5;

    {
        const __half* ga = Ab + (size_t)lar * K + las * 8;
        uint32_t sa = sbase + (uint32_t)(lar * 80 + las * 16);
        cp_async16(sa, ga);
        cp_async16(sa + 16, ga + 8);
        cp_async16(sbase + B_BASE + (uint32_t)(lbr * 80 + lbs * 16),
                   Bb + (size_t)lbr * K + lbs * 8);
        CP_COMMIT();
    }

    for (int c = 0; c < nch; c++) {
        int s = c & 1;
        if (c + 1 < nch) {
            int sn = (c + 1) & 1;
            int k0 = (c + 1) << 5;
            const __half* ga = Ab + (size_t)lar * K + k0 + las * 8;
            uint32_t sa = sbase + (uint32_t)(sn * A_STAGE_B + lar * 80 + las * 16);
            cp_async16(sa, ga);
            cp_async16(sa + 16, ga + 8);
            cp_async16(sbase + (uint32_t)(B_BASE + sn * B_STAGE_B + lbr * 80 + lbs * 16),
                       Bb + (size_t)lbr * K + k0 + lbs * 8);
            CP_COMMIT();
            CP_WAIT1();
        } else {
            CP_WAIT0();
        }
        __syncthreads();

        const __half* As = (const __half*)smem + s * (A_STAGE_B / 2);
        const __half* Bs = (const __half*)(smem + B_BASE) + s * (B_STAGE_B / 2);
#pragma unroll
        for (int ks = 0; ks < 2; ks++) {
            wmma::fragment<wmma::matrix_a, 16, 16, 16, __half, wmma::row_major> af[2];
            wmma::fragment<wmma::matrix_b, 16, 16, 16, __half, wmma::col_major> bf[2];
#pragma unroll
            for (int i = 0; i < 2; i++)
                wmma::load_matrix_sync(af[i], As + (wr * 32 + i * 16) * ASTR + ks * 16, ASTR);
#pragma unroll
            for (int j = 0; j < 2; j++)
                wmma::load_matrix_sync(bf[j], Bs + (wc * 32 + j * 16) * BSTR + ks * 16, BSTR);
#pragma unroll
            for (int i = 0; i < 2; i++)
#pragma unroll
                for (int j = 0; j < 2; j++)
                    wmma::mma_sync(cf[i][j], af[i], bf[j], cf[i][j]);
        }
        __syncthreads();
    }

#pragma unroll
    for (int i = 0; i < 2; i++)
#pragma unroll
        for (int j = 0; j < 2; j++)
            wmma::store_matrix_sync(stage + (wr * 32 + i * 16) * STG + wc * 32 + j * 16,
                                    cf[i][j], STG, wmma::mem_row_major);
    __syncthreads();

    for (int idx = tid; idx < 128 * 16; idx += 256) {
        int rr = idx >> 4, v = idx & 15;
        float4 val = *(float4*)&stage[rr * STG + 4 * v];
        int m  = row0 + rr;
        int c0 = col0 + 4 * v;
        float4 b4 = *(const float4*)&bias[c0];
        val.x += b4.x; val.y += b4.y; val.z += b4.z; val.w += b4.w;
        if (EPI == 0) {
            if (c0 < Cc) {   // q columns: fold in softmax scale
                val.x *= SCALEc; val.y *= SCALEc; val.z *= SCALEc; val.w *= SCALEc;
            }
            __half2 h0 = __floats2half2_rn(val.x, val.y);
            __half2 h1 = __floats2half2_rn(val.z, val.w);
            uint2 pk; pk.x = *(uint32_t*)&h0; pk.y = *(uint32_t*)&h1;
            *(uint2*)&outH[(size_t)m * N + c0] = pk;
        } else if (EPI == 1) {
            int b; int tok = win_to_token(m, b);
            size_t base = ((size_t)b * (Hc * Wc) + tok) * Cc + c0;
            float4 a4 = *(const float4*)&add[base];
            val.x += a4.x; val.y += a4.y; val.z += a4.z; val.w += a4.w;
            *(float4*)&outF[base] = val;
        } else if (EPI == 2) {
            const float inv_s2 = 0.70710678118654752f;
            val.x = 0.5f * val.x * (1.0f + erff(val.x * inv_s2));
            val.y = 0.5f * val.y * (1.0f + erff(val.y * inv_s2));
            val.z = 0.5f * val.z * (1.0f + erff(val.z * inv_s2));
            val.w = 0.5f * val.w * (1.0f + erff(val.w * inv_s2));
            __half2 h0 = __floats2half2_rn(val.x, val.y);
            __half2 h1 = __floats2half2_rn(val.z, val.w);
            uint2 pk; pk.x = *(uint32_t*)&h0; pk.y = *(uint32_t*)&h1;
            *(uint2*)&outH[(size_t)m * N + c0] = pk;
        } else {
            size_t base = (size_t)m * Cc + c0;
            float4 a4 = *(const float4*)&add[base];
            val.x += a4.x; val.y += a4.y; val.z += a4.z; val.w += a4.w;
            *(float4*)&outF[base] = val;
        }
    }
}

// ---------------- attention (wmma HMMA, 49 padded to 64) ----------------
#define QSTR 40
#define SSTR 72
#define PVSTR 40

__global__ void __launch_bounds__(256) attn_kernel(const __half* __restrict__ qkv,
                                                   const float* __restrict__ bm,
                                                   __half* __restrict__ out) {
    int bh = blockIdx.x;
    int b_ = bh / NHc;
    int h  = bh - b_ * NHc;
    int tid = threadIdx.x;
    int wid = tid >> 5, lane = tid & 31;

    __shared__ __half Qs[64 * QSTR];
    __shared__ __half Ks[64 * QSTR];
    __shared__ __half Vs[64 * QSTR];
    __shared__ float  Sf[64 * SSTR];
    __shared__ __half Ph[64 * SSTR];

    {
        int r = tid >> 2, seg = tid & 3;
        uint4 zz = make_uint4(0, 0, 0, 0);
        if (r < Nc) {
            const __half* src = qkv + ((size_t)b_ * Nc + r) * (3 * Cc) + h * HDc + seg * 8;
            *(uint4*)(Qs + r * QSTR + seg * 8) = *(const uint4*)src;
            *(uint4*)(Ks + r * QSTR + seg * 8) = *(const uint4*)(src + Cc);
            *(uint4*)(Vs + r * QSTR + seg * 8) = *(const uint4*)(src + 2 * Cc);
        } else {
            *(uint4*)(Qs + r * QSTR + seg * 8) = zz;
            *(uint4*)(Ks + r * QSTR + seg * 8) = zz;
            *(uint4*)(Vs + r * QSTR + seg * 8) = zz;
        }
    }
    __syncthreads();

    // ---- S = Q @ K^T (16 tiles, 2 per warp); Q pre-scaled in QKV GEMM ----
#pragma unroll
    for (int t = wid * 2; t < wid * 2 + 2; t++) {
        int tr = t >> 2, tc = t & 3;
        wmma::fragment<wmma::accumulator, 16, 16, 16, float> c;
        wmma::fill_fragment(c, 0.0f);
#pragma unroll
        for (int kt = 0; kt < 2; kt++) {
            wmma::fragment<wmma::matrix_a, 16, 16, 16, __half, wmma::row_major> a;
            wmma::fragment<wmma::matrix_b, 16, 16, 16, __half, wmma::col_major> bfr;
            wmma::load_matrix_sync(a,   Qs + (tr * 16) * QSTR + kt * 16, QSTR);
            wmma::load_matrix_sync(bfr, Ks + (tc * 16) * QSTR + kt * 16, QSTR);
            wmma::mma_sync(c, a, bfr, c);
        }
        wmma::store_matrix_sync(Sf + (tr * 16) * SSTR + tc * 16, c, SSTR, wmma::mem_row_major);
    }
    __syncthreads();

    // ---- softmax rows (fp32) using precomputed bias+mask table ----
    int wi = b_ & 63;
    int wt = (((wi >> 3) == 7) ? 1 : 0) | (((wi & 7) == 7) ? 2 : 0);
    const float* tab = bm + ((size_t)(wt * NHc + h)) * (Nc * Nc);
    for (int i = wid; i < Nc; i += 8) {
        float* row = Sf + i * SSTR;
        const float* trow = tab + i * Nc;
        int j1 = lane, j2 = lane + 32;
        float v1 = (j1 < Nc) ? row[j1] + trow[j1] : -1e30f;
        float v2 = (j2 < Nc) ? row[j2] + trow[j2] : -1e30f;
        float mx = fmaxf(v1, v2);
#pragma unroll
        for (int o = 16; o > 0; o >>= 1) mx = fmaxf(mx, __shfl_xor_sync(0xffffffffu, mx, o));
        float e1 = (j1 < Nc) ? __expf(v1 - mx) : 0.f;
        float e2 = (j2 < Nc) ? __expf(v2 - mx) : 0.f;
        float sum = e1 + e2;
#pragma unroll
        for (int o = 16; o > 0; o >>= 1) sum += __shfl_xor_sync(0xffffffffu, sum, o);
        float inv = 1.0f / sum;
        __half* prow = Ph + i * SSTR;
        prow[j1] = __float2half(e1 * inv);
        prow[j2] = __float2half(e2 * inv);
    }
    for (int idx = tid; idx < (64 - Nc) * 64; idx += 256) {
        int r = Nc + (idx >> 6), j = idx & 63;
        Ph[r * SSTR + j] = __float2half(0.f);
    }
    __syncthreads();

    // ---- out = P @ V (8 tiles, 1 per warp) ----
    {
        int tr = wid >> 1, tc = wid & 1;
        wmma::fragment<wmma::accumulator, 16, 16, 16, float> c;
        wmma::fill_fragment(c, 0.0f);
#pragma unroll
        for (int kt = 0; kt < 4; kt++) {
            wmma::fragment<wmma::matrix_a, 16, 16, 16, __half, wmma::row_major> a;
            wmma::fragment<wmma::matrix_b, 16, 16, 16, __half, wmma::row_major> bfr;
            wmma::load_matrix_sync(a,   Ph + (tr * 16) * SSTR + kt * 16, SSTR);
            wmma::load_matrix_sync(bfr, Vs + (kt * 16) * QSTR + tc * 16, QSTR);
            wmma::mma_sync(c, a, bfr, c);
        }
        __syncthreads();
        wmma::store_matrix_sync(Sf + (tr * 16) * PVSTR + tc * 16, c, PVSTR, wmma::mem_row_major);
    }
    __syncthreads();

    for (int idx = tid; idx < Nc * HDc; idx += 256) {
        int i = idx >> 5, d = idx & 31;
        out[((size_t)b_ * Nc + i) * Cc + h * HDc + d] = __float2half(Sf[i * PVSTR + d]);
    }
}

// ---------------- launch ----------------
extern "C" void kernel_launch(void* const* d_in, const int* in_sizes, int n_in,
                              void* d_out, int out_size) {
    const float* x       = (const float*)d_in[0];
    const float* norm1_g = (const float*)d_in[1];
    const float* norm1_b = (const float*)d_in[2];
    const float* qkv_w   = (const float*)d_in[3];
    const float* qkv_b   = (const float*)d_in[4];
    const float* proj_w  = (const float*)d_in[5];
    const float* proj_b  = (const float*)d_in[6];
    const float* rpb     = (const float*)d_in[7];
    const float* norm2_g = (const float*)d_in[8];
    const float* norm2_b = (const float*)d_in[9];
    const float* fc1_w   = (const float*)d_in[10];
    const float* fc1_b   = (const float*)d_in[11];
    const float* fc2_w   = (const float*)d_in[12];
    const float* fc2_b   = (const float*)d_in[13];
    float* outp = (float*)d_out;

    __half *p_xw, *p_qkv, *p_attn, *p_ln2, *p_fc1, *p_wqkv, *p_wproj, *p_wfc1, *p_wfc2;
    float *p_h, *p_bm;
    cudaGetSymbolAddress((void**)&p_xw,   g_xw_h);
    cudaGetSymbolAddress((void**)&p_qkv,  g_qkv_h);
    cudaGetSymbolAddress((void**)&p_attn, g_attn_h);
    cudaGetSymbolAddress((void**)&p_h,    g_h);
    cudaGetSymbolAddress((void**)&p_ln2,  g_ln2_h);
    cudaGetSymbolAddress((void**)&p_fc1,  g_fc1_h);
    cudaGetSymbolAddress((void**)&p_wqkv, g_wqkv_h);
    cudaGetSymbolAddress((void**)&p_wproj,g_wproj_h);
    cudaGetSymbolAddress((void**)&p_wfc1, g_wfc1_h);
    cudaGetSymbolAddress((void**)&p_wfc2, g_wfc2_h);
    cudaGetSymbolAddress((void**)&p_bm,   g_bm);

    const int ntotW = NQKV + NPRJ + NFC1 + NFC2;
    f2h4_kernel<<<(ntotW + 255) / 256, 256>>>(qkv_w, proj_w, fc1_w, fc2_w,
                                              p_wqkv, p_wproj, p_wfc1, p_wfc2);
    bm_kernel<<<(NBM + 255) / 256, 256>>>(rpb, p_bm);

    const int lnBlocks = (Mrows * 32 + 255) / 256;
    const int smemB = SMEM_TOT;

    // 1) LN1 + shift + window partition (-> fp16)
    ln_kernel<0><<<lnBlocks, 256>>>(x, norm1_g, norm1_b, p_xw);

    // 2) QKV GEMM (HMMA, pipelined) -> fp16, q pre-scaled
    hgemm_kernel<0><<<dim3(9, 784), 256, smemB>>>(p_xw, p_wqkv, qkv_b, nullptr,
                                                  nullptr, p_qkv, 3*Cc, Cc);

    // 3) windowed attention (wmma, table-driven bias+mask)
    attn_kernel<<<Bc * NWIN * NHc, 256>>>(p_qkv, p_bm, p_attn);

    // 4) proj GEMM + window reverse + roll + shortcut -> fp32 h
    hgemm_kernel<1><<<dim3(3, 784), 256, smemB>>>(p_attn, p_wproj, proj_b, x,
                                                  p_h, nullptr, Cc, Cc);

    // 5) LN2 (-> fp16)
    ln_kernel<1><<<lnBlocks, 256>>>(p_h, norm2_g, norm2_b, p_ln2);

    // 6) FC1 + GELU (-> fp16)
    hgemm_kernel<2><<<dim3(12, 784), 256, smemB>>>(p_ln2, p_wfc1, fc1_b, nullptr,
                                                   nullptr, p_fc1, HIDc, Cc);

    // 7) FC2 + residual -> fp32 out
    hgemm_kernel<3><<<dim3(3, 784), 256, smemB>>>(p_fc1, p_wfc2, fc2_b, p_h,
                                                  outp, nullptr, Cc, HIDc);
}

// round 16
// speedup vs baseline: 5.8889x; 1.1213x over previous
#include <cuda_runtime.h>
#include <cuda_fp16.h>
#include <mma.h>
#include <math.h>
#include <stdint.h>

using namespace nvcuda;

// ---------------- problem constants ----------------
#define Bc   32
#define Hc   56
#define Wc   56
#define Cc   192
#define WSc  7
#define SSc  3
#define NHc  6
#define Nc   49
#define HDc  32
#define HIDc 768
#define NWIN 64
#define Mrows (Bc * Hc * Wc)   // 100352
#define SCALEc 0.17677669529663687f
#define EPSc 1e-5f

// ---------------- scratch (device globals, no allocs) ----------------
__device__ __half g_xw_h  [(size_t)Mrows * Cc];
__device__ __half g_qkv_h [(size_t)Mrows * 3 * Cc];
__device__ __half g_attn_h[(size_t)Mrows * Cc];
__device__ float  g_h     [(size_t)Mrows * Cc];
__device__ __half g_ln2_h [(size_t)Mrows * Cc];
__device__ __half g_fc1_h [(size_t)Mrows * HIDc];
__device__ __half g_wqkv_h[3 * Cc * Cc];
__device__ __half g_wproj_h[Cc * Cc];
__device__ __half g_wfc1_h[HIDc * Cc];
__device__ __half g_wfc2_h[Cc * HIDc];
__device__ float  g_bm    [4 * NHc * Nc * Nc];

// ---------------- index helpers ----------------
__device__ __forceinline__ int win_to_token(int r, int& b) {
    int b_ = r / Nc;
    int n  = r - b_ * Nc;
    b = b_ >> 6;
    int wi = b_ & 63;
    int wr = wi >> 3, wc = wi & 7;
    int hs = wr * WSc + n / WSc;
    int ws = wc * WSc + n % WSc;
    int ho = hs + SSc; if (ho >= Hc) ho -= Hc;
    int wo = ws + SSc; if (wo >= Wc) wo -= Wc;
    return ho * Wc + wo;
}
__device__ __forceinline__ int regionOf(int p) {
    return (p < Hc - WSc) ? 0 : ((p < Hc - SSc) ? 1 : 2);
}

__device__ __forceinline__ uint32_t smem_u32(const void* p) {
    uint32_t a;
    asm("{ .reg .u64 t; cvta.to.shared.u64 t, %1; cvt.u32.u64 %0, t; }" : "=r"(a) : "l"(p));
    return a;
}
__device__ __forceinline__ void cp_async16(uint32_t saddr, const void* g) {
    asm volatile("cp.async.cg.shared.global [%0], [%1], 16;" :: "r"(saddr), "l"(g));
}
#define CP_COMMIT() asm volatile("cp.async.commit_group;" ::: "memory")
#define CP_WAIT1()  asm volatile("cp.async.wait_group 1;" ::: "memory")
#define CP_WAIT0()  asm volatile("cp.async.wait_group 0;" ::: "memory")

// ---------------- precompute combined bias+mask table ----------------
#define NBM (4 * NHc * Nc * Nc)
__global__ void __launch_bounds__(256) bm_kernel(const float* __restrict__ rpb,
                                                 float* __restrict__ bm) {
    int idx = blockIdx.x * blockDim.x + threadIdx.x;
    if (idx >= NBM) return;
    int j = idx % Nc;
    int t = idx / Nc;
    int i = t % Nc;  t /= Nc;
    int h = t % NHc;
    int wt = t / NHc;
    int ri = i / WSc, ci = i % WSc;
    int rj = j / WSc, cj = j % WSc;
    int rel = (ri - rj + WSc - 1) * (2 * WSc - 1) + (ci - cj + WSc - 1);
    float v = rpb[rel * NHc + h];
    int regRi = (wt & 1) ? regionOf(49 + ri) : 0;
    int regCi = (wt & 2) ? regionOf(49 + ci) : 0;
    int regRj = (wt & 1) ? regionOf(49 + rj) : 0;
    int regCj = (wt & 2) ? regionOf(49 + cj) : 0;
    if (regRi * 3 + regCi != regRj * 3 + regCj) v -= 100.0f;
    bm[idx] = v;
}

// ---------------- fused weight conversion ----------------
#define NQKV (3 * Cc * Cc)
#define NPRJ (Cc * Cc)
#define NFC1 (HIDc * Cc)
#define NFC2 (Cc * HIDc)
__global__ void __launch_bounds__(256) f2h4_kernel(const float* __restrict__ w0,
                                                   const float* __restrict__ w1,
                                                   const float* __restrict__ w2,
                                                   const float* __restrict__ w3,
                                                   __half* __restrict__ o0,
                                                   __half* __restrict__ o1,
                                                   __half* __restrict__ o2,
                                                   __half* __restrict__ o3) {
    int i = blockIdx.x * blockDim.x + threadIdx.x;
    if (i < NQKV) o0[i] = __float2half(w0[i]);
    int j = i - NQKV;
    if (j >= 0 && j < NPRJ) o1[j] = __float2half(w1[j]);
    int k = j - NPRJ;
    if (k >= 0 && k < NFC1) o2[k] = __float2half(w2[k]);
    int l = k - NFC1;
    if (l >= 0 && l < NFC2) o3[l] = __float2half(w3[l]);
}

// ---------------- LayerNorm kernels (warp per row), output fp16 ----------------
template<int MODE>
__global__ void __launch_bounds__(256) ln_kernel(const float* __restrict__ x,
                                                 const float* __restrict__ g,
                                                 const float* __restrict__ bta,
                                                 __half* __restrict__ out) {
    int warp = (blockIdx.x * blockDim.x + threadIdx.x) >> 5;
    int lane = threadIdx.x & 31;
    if (warp >= Mrows) return;
    const float* src;
    if (MODE == 0) {
        int b; int tok = win_to_token(warp, b);
        src = x + ((size_t)b * (Hc * Wc) + tok) * Cc;
    } else {
        src = x + (size_t)warp * Cc;
    }
    float e[6]; float s = 0.f, ss = 0.f;
#pragma unroll
    for (int k = 0; k < 6; k++) { e[k] = src[lane + 32 * k]; s += e[k]; ss += e[k] * e[k]; }
#pragma unroll
    for (int o = 16; o > 0; o >>= 1) {
        s  += __shfl_xor_sync(0xffffffffu, s,  o);
        ss += __shfl_xor_sync(0xffffffffu, ss, o);
    }
    float mu = s * (1.f / Cc);
    float var = ss * (1.f / Cc) - mu * mu;
    float rs = rsqrtf(var + EPSc);
    __half* dst = out + (size_t)warp * Cc;
#pragma unroll
    for (int k = 0; k < 6; k++) {
        int c = lane + 32 * k;
        dst[c] = __float2half((e[k] - mu) * rs * g[c] + bta[c]);
    }
}

// ---------------- wmma HMMA GEMM: 128 threads, warp tile 64x32, 3-stage cp.async ----
#define ASTR 40
#define BSTR 40
#define STG  72
#define A_STAGE_B (128 * ASTR * 2)           // 10240
#define B_STAGE_B (64 * BSTR * 2)            // 5120
#define STAGE_TOT (A_STAGE_B + B_STAGE_B)    // 15360
#define SMEM_TOT  (3 * STAGE_TOT)            // 46080 (>= 128*72*4 = 36864 epilogue)

template<int EPI>
__global__ void __launch_bounds__(128) hgemm_kernel(const __half* __restrict__ A,
                                                    const __half* __restrict__ Bw,
                                                    const float* __restrict__ bias,
                                                    const float* __restrict__ add,
                                                    float* __restrict__ outF,
                                                    __half* __restrict__ outH,
                                                    int N, int K) {
    extern __shared__ char smem[];
    float* stage = (float*)smem;
    uint32_t sbase = smem_u32(smem);

    int tid = threadIdx.x;
    int wid = tid >> 5;
    int wr = wid & 1;          // M half (64 rows)
    int wc = wid >> 1;         // N half (32 cols)
    int row0 = blockIdx.y * 128;
    int col0 = blockIdx.x * 64;

    const __half* Ab = A  + (size_t)row0 * K;
    const __half* Bb = Bw + (size_t)col0 * K;

    wmma::fragment<wmma::accumulator, 16, 16, 16, float> cf[4][2];
#pragma unroll
    for (int i = 0; i < 4; i++)
#pragma unroll
        for (int j = 0; j < 2; j++)
            wmma::fill_fragment(cf[i][j], 0.0f);

    int nch = K >> 5;

    auto issue = [&](int c, int st) {
        int k0 = c << 5;
        uint32_t abase = sbase + (uint32_t)(st * STAGE_TOT);
        uint32_t bbase = abase + A_STAGE_B;
#pragma unroll
        for (int t = 0; t < 4; t++) {          // A: 512 16B chunks / 128 thr
            int idx = tid + t * 128;
            int r = idx >> 2, seg = idx & 3;
            cp_async16(abase + (uint32_t)(r * 80 + seg * 16),
                       Ab + (size_t)r * K + k0 + seg * 8);
        }
#pragma unroll
        for (int t = 0; t < 2; t++) {          // B: 256 16B chunks
            int idx = tid + t * 128;
            int r = idx >> 2, seg = idx & 3;
            cp_async16(bbase + (uint32_t)(r * 80 + seg * 16),
                       Bb + (size_t)r * K + k0 + seg * 8);
        }
        CP_COMMIT();
    };

    issue(0, 0);
    if (nch > 1) issue(1, 1);

    for (int c = 0; c < nch; c++) {
        // committed-but-unwaited: chunks c and (c+1 if issued). Guarantee chunk c:
        if (c + 1 < nch) CP_WAIT1();
        else             CP_WAIT0();
        __syncthreads();                       // chunk c ready; stage (c+2)%3 reads retired
        if (c + 2 < nch) issue(c + 2, (c + 2) % 3);

        int st = c % 3;
        const __half* As = (const __half*)(smem + st * STAGE_TOT);
        const __half* Bs = (const __half*)(smem + st * STAGE_TOT + A_STAGE_B);
#pragma unroll
        for (int ks = 0; ks < 2; ks++) {
            wmma::fragment<wmma::matrix_a, 16, 16, 16, __half, wmma::row_major> af[4];
            wmma::fragment<wmma::matrix_b, 16, 16, 16, __half, wmma::col_major> bf[2];
#pragma unroll
            for (int i = 0; i < 4; i++)
                wmma::load_matrix_sync(af[i], As + (wr * 64 + i * 16) * ASTR + ks * 16, ASTR);
#pragma unroll
            for (int j = 0; j < 2; j++)
                wmma::load_matrix_sync(bf[j], Bs + (wc * 32 + j * 16) * BSTR + ks * 16, BSTR);
#pragma unroll
            for (int i = 0; i < 4; i++)
#pragma unroll
                for (int j = 0; j < 2; j++)
                    wmma::mma_sync(cf[i][j], af[i], bf[j], cf[i][j]);
        }
    }
    __syncthreads();   // AB reads done; smem becomes epilogue stage

#pragma unroll
    for (int i = 0; i < 4; i++)
#pragma unroll
        for (int j = 0; j < 2; j++)
            wmma::store_matrix_sync(stage + (wr * 64 + i * 16) * STG + wc * 32 + j * 16,
                                    cf[i][j], STG, wmma::mem_row_major);
    __syncthreads();

    for (int idx = tid; idx < 128 * 16; idx += 128) {
        int rr = idx >> 4, v = idx & 15;
        float4 val = *(float4*)&stage[rr * STG + 4 * v];
        int m  = row0 + rr;
        int c0 = col0 + 4 * v;
        float4 b4 = *(const float4*)&bias[c0];
        val.x += b4.x; val.y += b4.y; val.z += b4.z; val.w += b4.w;
        if (EPI == 0) {
            if (c0 < Cc) {
                val.x *= SCALEc; val.y *= SCALEc; val.z *= SCALEc; val.w *= SCALEc;
            }
            __half2 h0 = __floats2half2_rn(val.x, val.y);
            __half2 h1 = __floats2half2_rn(val.z, val.w);
            uint2 pk; pk.x = *(uint32_t*)&h0; pk.y = *(uint32_t*)&h1;
            *(uint2*)&outH[(size_t)m * N + c0] = pk;
        } else if (EPI == 1) {
            int b; int tok = win_to_token(m, b);
            size_t base = ((size_t)b * (Hc * Wc) + tok) * Cc + c0;
            float4 a4 = *(const float4*)&add[base];
            val.x += a4.x; val.y += a4.y; val.z += a4.z; val.w += a4.w;
            *(float4*)&outF[base] = val;
        } else if (EPI == 2) {
            const float inv_s2 = 0.70710678118654752f;
            val.x = 0.5f * val.x * (1.0f + erff(val.x * inv_s2));
            val.y = 0.5f * val.y * (1.0f + erff(val.y * inv_s2));
            val.z = 0.5f * val.z * (1.0f + erff(val.z * inv_s2));
            val.w = 0.5f * val.w * (1.0f + erff(val.w * inv_s2));
            __half2 h0 = __floats2half2_rn(val.x, val.y);
            __half2 h1 = __floats2half2_rn(val.z, val.w);
            uint2 pk; pk.x = *(uint32_t*)&h0; pk.y = *(uint32_t*)&h1;
            *(uint2*)&outH[(size_t)m * N + c0] = pk;
        } else {
            size_t base = (size_t)m * Cc + c0;
            float4 a4 = *(const float4*)&add[base];
            val.x += a4.x; val.y += a4.y; val.z += a4.z; val.w += a4.w;
            *(float4*)&outF[base] = val;
        }
    }
}

// ---------------- attention (wmma HMMA, 49 padded to 64) ----------------
#define QSTR 40
#define SSTR 72
#define PVSTR 40

__global__ void __launch_bounds__(256) attn_kernel(const __half* __restrict__ qkv,
                                                   const float* __restrict__ bm,
                                                   __half* __restrict__ out) {
    int bh = blockIdx.x;
    int b_ = bh / NHc;
    int h  = bh - b_ * NHc;
    int tid = threadIdx.x;
    int wid = tid >> 5, lane = tid & 31;

    __shared__ __half Qs[64 * QSTR];
    __shared__ __half Ks[64 * QSTR];
    __shared__ __half Vs[64 * QSTR];
    __shared__ float  Sf[64 * SSTR];
    __shared__ __half Ph[64 * SSTR];

    {
        int r = tid >> 2, seg = tid & 3;
        uint4 zz = make_uint4(0, 0, 0, 0);
        if (r < Nc) {
            const __half* src = qkv + ((size_t)b_ * Nc + r) * (3 * Cc) + h * HDc + seg * 8;
            *(uint4*)(Qs + r * QSTR + seg * 8) = *(const uint4*)src;
            *(uint4*)(Ks + r * QSTR + seg * 8) = *(const uint4*)(src + Cc);
            *(uint4*)(Vs + r * QSTR + seg * 8) = *(const uint4*)(src + 2 * Cc);
        } else {
            *(uint4*)(Qs + r * QSTR + seg * 8) = zz;
            *(uint4*)(Ks + r * QSTR + seg * 8) = zz;
            *(uint4*)(Vs + r * QSTR + seg * 8) = zz;
        }
    }
    __syncthreads();

#pragma unroll
    for (int t = wid * 2; t < wid * 2 + 2; t++) {
        int tr = t >> 2, tc = t & 3;
        wmma::fragment<wmma::accumulator, 16, 16, 16, float> c;
        wmma::fill_fragment(c, 0.0f);
#pragma unroll
        for (int kt = 0; kt < 2; kt++) {
            wmma::fragment<wmma::matrix_a, 16, 16, 16, __half, wmma::row_major> a;
            wmma::fragment<wmma::matrix_b, 16, 16, 16, __half, wmma::col_major> bfr;
            wmma::load_matrix_sync(a,   Qs + (tr * 16) * QSTR + kt * 16, QSTR);
            wmma::load_matrix_sync(bfr, Ks + (tc * 16) * QSTR + kt * 16, QSTR);
            wmma::mma_sync(c, a, bfr, c);
        }
        wmma::store_matrix_sync(Sf + (tr * 16) * SSTR + tc * 16, c, SSTR, wmma::mem_row_major);
    }
    __syncthreads();

    int wi = b_ & 63;
    int wt = (((wi >> 3) == 7) ? 1 : 0) | (((wi & 7) == 7) ? 2 : 0);
    const float* tab = bm + ((size_t)(wt * NHc + h)) * (Nc * Nc);
    for (int i = wid; i < Nc; i += 8) {
        float* row = Sf + i * SSTR;
        const float* trow = tab + i * Nc;
        int j1 = lane, j2 = lane + 32;
        float v1 = (j1 < Nc) ? row[j1] + trow[j1] : -1e30f;
        float v2 = (j2 < Nc) ? row[j2] + trow[j2] : -1e30f;
        float mx = fmaxf(v1, v2);
#pragma unroll
        for (int o = 16; o > 0; o >>= 1) mx = fmaxf(mx, __shfl_xor_sync(0xffffffffu, mx, o));
        float e1 = (j1 < Nc) ? __expf(v1 - mx) : 0.f;
        float e2 = (j2 < Nc) ? __expf(v2 - mx) : 0.f;
        float sum = e1 + e2;
#pragma unroll
        for (int o = 16; o > 0; o >>= 1) sum += __shfl_xor_sync(0xffffffffu, sum, o);
        float inv = 1.0f / sum;
        __half* prow = Ph + i * SSTR;
        prow[j1] = __float2half(e1 * inv);
        prow[j2] = __float2half(e2 * inv);
    }
    for (int idx = tid; idx < (64 - Nc) * 64; idx += 256) {
        int r = Nc + (idx >> 6), j = idx & 63;
        Ph[r * SSTR + j] = __float2half(0.f);
    }
    __syncthreads();

    {
        int tr = wid >> 1, tc = wid & 1;
        wmma::fragment<wmma::accumulator, 16, 16, 16, float> c;
        wmma::fill_fragment(c, 0.0f);
#pragma unroll
        for (int kt = 0; kt < 4; kt++) {
            wmma::fragment<wmma::matrix_a, 16, 16, 16, __half, wmma::row_major> a;
            wmma::fragment<wmma::matrix_b, 16, 16, 16, __half, wmma::row_major> bfr;
            wmma::load_matrix_sync(a,   Ph + (tr * 16) * SSTR + kt * 16, SSTR);
            wmma::load_matrix_sync(bfr, Vs + (kt * 16) * QSTR + tc * 16, QSTR);
            wmma::mma_sync(c, a, bfr, c);
        }
        __syncthreads();
        wmma::store_matrix_sync(Sf + (tr * 16) * PVSTR + tc * 16, c, PVSTR, wmma::mem_row_major);
    }
    __syncthreads();

    for (int idx = tid; idx < Nc * HDc; idx += 256) {
        int i = idx >> 5, d = idx & 31;
        out[((size_t)b_ * Nc + i) * Cc + h * HDc + d] = __float2half(Sf[i * PVSTR + d]);
    }
}

// ---------------- launch ----------------
extern "C" void kernel_launch(void* const* d_in, const int* in_sizes, int n_in,
                              void* d_out, int out_size) {
    const float* x       = (const float*)d_in[0];
    const float* norm1_g = (const float*)d_in[1];
    const float* norm1_b = (const float*)d_in[2];
    const float* qkv_w   = (const float*)d_in[3];
    const float* qkv_b   = (const float*)d_in[4];
    const float* proj_w  = (const float*)d_in[5];
    const float* proj_b  = (const float*)d_in[6];
    const float* rpb     = (const float*)d_in[7];
    const float* norm2_g = (const float*)d_in[8];
    const float* norm2_b = (const float*)d_in[9];
    const float* fc1_w   = (const float*)d_in[10];
    const float* fc1_b   = (const float*)d_in[11];
    const float* fc2_w   = (const float*)d_in[12];
    const float* fc2_b   = (const float*)d_in[13];
    float* outp = (float*)d_out;

    __half *p_xw, *p_qkv, *p_attn, *p_ln2, *p_fc1, *p_wqkv, *p_wproj, *p_wfc1, *p_wfc2;
    float *p_h, *p_bm;
    cudaGetSymbolAddress((void**)&p_xw,   g_xw_h);
    cudaGetSymbolAddress((void**)&p_qkv,  g_qkv_h);
    cudaGetSymbolAddress((void**)&p_attn, g_attn_h);
    cudaGetSymbolAddress((void**)&p_h,    g_h);
    cudaGetSymbolAddress((void**)&p_ln2,  g_ln2_h);
    cudaGetSymbolAddress((void**)&p_fc1,  g_fc1_h);
    cudaGetSymbolAddress((void**)&p_wqkv, g_wqkv_h);
    cudaGetSymbolAddress((void**)&p_wproj,g_wproj_h);
    cudaGetSymbolAddress((void**)&p_wfc1, g_wfc1_h);
    cudaGetSymbolAddress((void**)&p_wfc2, g_wfc2_h);
    cudaGetSymbolAddress((void**)&p_bm,   g_bm);

    const int ntotW = NQKV + NPRJ + NFC1 + NFC2;
    f2h4_kernel<<<(ntotW + 255) / 256, 256>>>(qkv_w, proj_w, fc1_w, fc2_w,
                                              p_wqkv, p_wproj, p_wfc1, p_wfc2);
    bm_kernel<<<(NBM + 255) / 256, 256>>>(rpb, p_bm);

    const int lnBlocks = (Mrows * 32 + 255) / 256;

    // 1) LN1 + shift + window partition (-> fp16)
    ln_kernel<0><<<lnBlocks, 256>>>(x, norm1_g, norm1_b, p_xw);

    // 2) QKV GEMM -> fp16, q pre-scaled
    hgemm_kernel<0><<<dim3(9, 784), 128, SMEM_TOT>>>(p_xw, p_wqkv, qkv_b, nullptr,
                                                     nullptr, p_qkv, 3*Cc, Cc);

    // 3) windowed attention
    attn_kernel<<<Bc * NWIN * NHc, 256>>>(p_qkv, p_bm, p_attn);

    // 4) proj GEMM + window reverse + roll + shortcut -> fp32 h
    hgemm_kernel<1><<<dim3(3, 784), 128, SMEM_TOT>>>(p_attn, p_wproj, proj_b, x,
                                                     p_h, nullptr, Cc, Cc);

    // 5) LN2 (-> fp16)
    ln_kernel<1><<<lnBlocks, 256>>>(p_h, norm2_g, norm2_b, p_ln2);

    // 6) FC1 + GELU (-> fp16)
    hgemm_kernel<2><<<dim3(12, 784), 128, SMEM_TOT>>>(p_ln2, p_wfc1, fc1_b, nullptr,
                                                      nullptr, p_fc1, HIDc, Cc);

    // 7) FC2 + residual -> fp32 out
    hgemm_kernel<3><<<dim3(3, 784), 128, SMEM_TOT>>>(p_fc1, p_wfc2, fc2_b, p_h,
                                                     outp, nullptr, Cc, HIDc);
}